// round 3
// baseline (speedup 1.0000x reference)
#include <cuda_runtime.h>
#include <math.h>

// Problem constants
#define NB 32          // batch
#define CC 256         // channels
#define HW 4096        // H*W
#define GG 4           // groups
#define DD 64          // channels per group
#define MMTOT 131072   // m = NB*HW
#define CHUNKS 8       // hw chunks per (n,g)
#define TK 512         // hw per chunk
#define SUB 64         // k-subtile
#define NSUB 8         // TK/SUB
#define LDA 68         // padded smem row stride (statsgram tile)

typedef unsigned long long u64;

__device__ __forceinline__ u64 pack2(float lo, float hi) {
    u64 r; asm("mov.b64 %0, {%1,%2};" : "=l"(r) : "f"(lo), "f"(hi)); return r;
}
__device__ __forceinline__ void unpack2(u64 v, float& lo, float& hi) {
    asm("mov.b64 {%0,%1}, %2;" : "=f"(lo), "=f"(hi) : "l"(v));
}
__device__ __forceinline__ void fma2(u64& d, u64 a, u64 b) {
    asm("fma.rn.f32x2 %0, %1, %2, %0;" : "+l"(d) : "l"(a), "l"(b));
}

// Scratch (device globals; no allocation allowed)
__device__ float g_sum[NB*CC];
__device__ float g_sumsq[NB*CC];
__device__ float g_gram[GG*DD*DD];
__device__ float g_sigman[GG*DD*DD];
__device__ float g_pw[GG*DD*DD];     // w * P per group
__device__ float g_y[NB*CC];         // sigmoid MLP output
__device__ float g_varsum;           // sum of x_var over all (n,c)

// ---------------------------------------------------------------------------
__global__ void k_zero() {
    int i = blockIdx.x * blockDim.x + threadIdx.x;
    if (i < NB*CC) { g_sum[i] = 0.f; g_sumsq[i] = 0.f; }
    if (i < GG*DD*DD) g_gram[i] = 0.f;
    if (i == 0) g_varsum = 0.f;
}

// ---------------------------------------------------------------------------
// Pass 1: read X once. Per-(n,c) sum & sumsq + per-group uncentered Gram.
// 64 threads/block, each thread an 8x8 Gram tile, f32x2 packed FMAs.
// Grid: (CHUNKS, GG, NB).
__global__ __launch_bounds__(64, 8) void k_statsgram(const float* __restrict__ X) {
    __shared__ float As[SUB][LDA];   // As[k][ch] (transposed tile)
    int n = blockIdx.z, g = blockIdx.y, ch = blockIdx.x;
    const float* base = X + ((size_t)(n*CC + g*DD))*HW + (size_t)ch*TK;
    int t = threadIdx.x;             // 0..63
    int r0 = (t >> 3) << 3;          // 8 row-groups
    int c0 = (t & 7) << 3;           // 8 col-groups

    u64 acc[8][4];
    #pragma unroll
    for (int i = 0; i < 8; i++)
        #pragma unroll
        for (int j = 0; j < 4; j++) acc[i][j] = 0ULL;
    float s1 = 0.f, s2 = 0.f;        // stats for channel t

    for (int sub = 0; sub < NSUB; sub++) {
        if (sub) __syncthreads();
        // load 64x64 tile (coalesced float4), transpose into As[k][ch]
        #pragma unroll
        for (int i = 0; i < 16; i++) {
            int idx = t + i*64;
            int c   = idx >> 4;
            int k4  = (idx & 15) << 2;
            float4 v = *(const float4*)(base + (size_t)c*HW + sub*SUB + k4);
            As[k4+0][c] = v.x; As[k4+1][c] = v.y;
            As[k4+2][c] = v.z; As[k4+3][c] = v.w;
        }
        __syncthreads();

        // stats for channel t (conflict-free: consecutive lanes, consecutive banks)
        float cs = 0.f, cq = 0.f;
        #pragma unroll 8
        for (int k = 0; k < SUB; k++) {
            float v = As[k][t];
            cs += v; cq += v*v;
        }
        s1 += cs; s2 += cq;

        // Gram: 8x8 register tile per thread, packed f32x2
        #pragma unroll 4
        for (int k = 0; k < SUB; k++) {
            float4 a0 = *(const float4*)&As[k][r0];
            float4 a1 = *(const float4*)&As[k][r0+4];
            const u64* bp = (const u64*)&As[k][c0];
            u64 b0 = bp[0], b1 = bp[1], b2v = bp[2], b3 = bp[3];
            float av[8] = {a0.x,a0.y,a0.z,a0.w,a1.x,a1.y,a1.z,a1.w};
            #pragma unroll
            for (int ri = 0; ri < 8; ri++) {
                u64 a2 = pack2(av[ri], av[ri]);
                fma2(acc[ri][0], a2, b0);
                fma2(acc[ri][1], a2, b1);
                fma2(acc[ri][2], a2, b2v);
                fma2(acc[ri][3], a2, b3);
            }
        }
    }

    atomicAdd(&g_sum[n*CC + g*DD + t],   s1);
    atomicAdd(&g_sumsq[n*CC + g*DD + t], s2);

    float* gg = &g_gram[g*DD*DD];
    #pragma unroll
    for (int ri = 0; ri < 8; ri++)
        #pragma unroll
        for (int cj = 0; cj < 4; cj++) {
            float lo, hi;
            unpack2(acc[ri][cj], lo, hi);
            atomicAdd(&gg[(r0+ri)*DD + c0 + 2*cj],     lo);
            atomicAdd(&gg[(r0+ri)*DD + c0 + 2*cj + 1], hi);
        }
}

// ---------------------------------------------------------------------------
// Per-n MLP: x_var -> fc1 -> LayerNorm -> relu -> fc2 -> sigmoid = y
__global__ __launch_bounds__(256) void k_reweight(const float* __restrict__ fc1,
                                                  const float* __restrict__ lng,
                                                  const float* __restrict__ lnb,
                                                  const float* __restrict__ fc2) {
    __shared__ float sv[CC];
    __shared__ float sh[DD];
    __shared__ float warpsum[8];
    __shared__ float sred[2];
    int n = blockIdx.x, t = threadIdx.x;

    float s  = g_sum[n*CC + t];
    float ss = g_sumsq[n*CC + t];
    float var = (ss - s*s*(1.0f/HW)) * (1.0f/(HW - 1));   // ddof=1
    sv[t] = var;

    float vs = var;
    #pragma unroll
    for (int o = 16; o; o >>= 1) vs += __shfl_xor_sync(0xffffffffu, vs, o);
    if ((t & 31) == 0) warpsum[t >> 5] = vs;
    __syncthreads();
    if (t == 0) {
        float tot = 0.f;
        #pragma unroll
        for (int i = 0; i < 8; i++) tot += warpsum[i];
        atomicAdd(&g_varsum, tot);
    }

    int w = t >> 5, l = t & 31;
    for (int kk = 0; kk < 8; kk++) {
        int k = w*8 + kk;
        float acc = 0.f;
        for (int c = l; c < CC; c += 32) acc += sv[c] * fc1[k*CC + c];
        #pragma unroll
        for (int o = 16; o; o >>= 1) acc += __shfl_xor_sync(0xffffffffu, acc, o);
        if (l == 0) sh[k] = acc;
    }
    __syncthreads();

    if (w == 0) {
        float h1 = sh[l], h2 = sh[l + 32];
        float su = h1 + h2, q = h1*h1 + h2*h2;
        #pragma unroll
        for (int o = 16; o; o >>= 1) {
            su += __shfl_xor_sync(0xffffffffu, su, o);
            q  += __shfl_xor_sync(0xffffffffu, q,  o);
        }
        float mu = su * (1.0f/DD);
        float vr = q * (1.0f/DD) - mu*mu;
        if (l == 0) { sred[0] = mu; sred[1] = rsqrtf(vr + 1e-5f); }
    }
    __syncthreads();
    float mu = sred[0], rstd = sred[1];
    if (t < DD) {
        float hh = (sh[t] - mu) * rstd * lng[t] + lnb[t];
        sh[t] = fmaxf(hh, 0.f);
    }
    __syncthreads();

    float acc = 0.f;
    #pragma unroll 8
    for (int k = 0; k < DD; k++) acc += sh[k] * fc2[t*DD + k];
    g_y[n*CC + t] = 1.0f / (1.0f + expf(-acc));
}

// ---------------------------------------------------------------------------
// Sigma_N per group
__global__ __launch_bounds__(256) void k_sigma() {
    int g = blockIdx.x, t = threadIdx.x;
    __shared__ float smean[DD];
    __shared__ float sS[DD*DD];
    __shared__ float strace;
    if (t < DD) {
        float s = 0.f;
        #pragma unroll 8
        for (int n = 0; n < NB; n++) s += g_sum[n*CC + g*DD + t];
        smean[t] = s * (1.0f/(float)MMTOT);
    }
    if (t == 0) strace = 0.f;
    __syncthreads();
    float tr = 0.f;
    #pragma unroll
    for (int i = 0; i < 16; i++) {
        int idx = t + i*256;
        int r = idx >> 6, c = idx & 63;
        float v = 1e-5f * (g_gram[g*DD*DD + idx] - (float)MMTOT * smean[r] * smean[c]);
        if (r == c) { v += 1.0f/(float)MMTOT; tr += v; }
        sS[idx] = v;
    }
    #pragma unroll
    for (int o = 16; o; o >>= 1) tr += __shfl_xor_sync(0xffffffffu, tr, o);
    if ((t & 31) == 0) atomicAdd(&strace, tr);
    __syncthreads();
    float rtr = 1.0f / strace;
    #pragma unroll
    for (int i = 0; i < 16; i++) {
        int idx = t + i*256;
        g_sigman[g*DD*DD + idx] = sS[idx] * rtr;
    }
}

// ---------------------------------------------------------------------------
// Newton-Schulz (T=3): P = -0.5 P + 1.5 (P@P@P@Sigma_N). One block per group.
__device__ __forceinline__ void mm_acc(float acc[4][4], const float* A,
                                       const float* B, int tx, int ty) {
    #pragma unroll
    for (int i = 0; i < 4; i++)
        #pragma unroll
        for (int j = 0; j < 4; j++) acc[i][j] = 0.f;
    #pragma unroll 8
    for (int k = 0; k < DD; k++) {
        float a[4];
        #pragma unroll
        for (int ri = 0; ri < 4; ri++) a[ri] = A[((ty<<2)+ri)*DD + k];
        float4 bv = *(const float4*)&B[k*DD + (tx<<2)];
        float b[4] = {bv.x, bv.y, bv.z, bv.w};
        #pragma unroll
        for (int ri = 0; ri < 4; ri++)
            #pragma unroll
            for (int cj = 0; cj < 4; cj++)
                acc[ri][cj] += a[ri]*b[cj];
    }
}

__global__ __launch_bounds__(256) void k_ns(const float* __restrict__ xw) {
    __shared__ float sm[3*DD*DD];   // 49152 B
    float* sP = sm;
    float* sS = sm + DD*DD;
    float* sT = sm + 2*DD*DD;
    int g = blockIdx.x, t = threadIdx.x;
    int tx = t & 15, ty = t >> 4;

    #pragma unroll
    for (int i = 0; i < 16; i++) {
        int idx = t + i*256;
        sS[idx] = g_sigman[g*DD*DD + idx];
        sP[idx] = ((idx >> 6) == (idx & 63)) ? 1.0f : 0.0f;
    }
    __syncthreads();

    for (int it = 0; it < 3; it++) {
        float t1[4][4];
        mm_acc(t1, sP, sP, tx, ty);                 // T = P@P
        #pragma unroll
        for (int ri = 0; ri < 4; ri++)
            #pragma unroll
            for (int cj = 0; cj < 4; cj++)
                sT[((ty<<2)+ri)*DD + (tx<<2)+cj] = t1[ri][cj];
        __syncthreads();

        float p3[4][4];
        mm_acc(p3, sT, sP, tx, ty);                 // P^3 = T@P (in regs)
        float pold[4][4];
        #pragma unroll
        for (int ri = 0; ri < 4; ri++)
            #pragma unroll
            for (int cj = 0; cj < 4; cj++)
                pold[ri][cj] = sP[((ty<<2)+ri)*DD + (tx<<2)+cj];
        __syncthreads();
        #pragma unroll
        for (int ri = 0; ri < 4; ri++)
            #pragma unroll
            for (int cj = 0; cj < 4; cj++)
                sP[((ty<<2)+ri)*DD + (tx<<2)+cj] = p3[ri][cj];   // P <- P^3
        __syncthreads();

        float f[4][4];
        mm_acc(f, sP, sS, tx, ty);                  // P^3 @ Sigma_N
        __syncthreads();
        #pragma unroll
        for (int ri = 0; ri < 4; ri++)
            #pragma unroll
            for (int cj = 0; cj < 4; cj++)
                sP[((ty<<2)+ri)*DD + (tx<<2)+cj] =
                    -0.5f*pold[ri][cj] + 1.5f*f[ri][cj];
        __syncthreads();
    }

    float w = 1.0f / (1.0f + expf(-xw[0]));
    #pragma unroll
    for (int i = 0; i < 16; i++) {
        int idx = t + i*256;
        g_pw[g*DD*DD + idx] = w * sP[idx];
    }
}

// ---------------------------------------------------------------------------
// Pass 2: out = w*(P@x) + (1-w)*(y/scale)*X, fused.
// 64 threads/block, 8x8 per-thread register tile, f32x2 packed FMAs.
// Grid: (CHUNKS, GG, NB).
__global__ __launch_bounds__(64, 7) void k_apply(const float* __restrict__ X,
                                                 const float* __restrict__ xw,
                                                 float* __restrict__ out) {
    __shared__ float Pt[DD][DD];   // Pt[d][r] (transposed w*P), unpadded
    __shared__ float As[DD][DD];   // As[d][k] X tile, unpadded
    int n = blockIdx.z, g = blockIdx.y, ch = blockIdx.x;
    int t = threadIdx.x;
    int r0 = (t >> 3) << 3;
    int c0 = (t & 7) << 3;
    const float* base = X   + ((size_t)(n*CC + g*DD))*HW + (size_t)ch*TK;
    float*      obase = out + ((size_t)(n*CC + g*DD))*HW + (size_t)ch*TK;

    // load wP transposed into smem (one-time; conflicts acceptable)
    #pragma unroll
    for (int i = 0; i < 16; i++) {
        int idx = t + i*64;
        int r  = idx >> 4;
        int d0 = (idx & 15) << 2;
        float4 v = *(const float4*)&g_pw[g*DD*DD + r*DD + d0];
        Pt[d0+0][r] = v.x; Pt[d0+1][r] = v.y;
        Pt[d0+2][r] = v.z; Pt[d0+3][r] = v.w;
    }
    float w = 1.0f / (1.0f + expf(-xw[0]));
    float rscale = rsqrtf(g_varsum * (1.0f/(float)(NB*CC)));
    float coef[8];
    #pragma unroll
    for (int ri = 0; ri < 8; ri++)
        coef[ri] = (1.0f - w) * g_y[n*CC + g*DD + r0 + ri] * rscale;
    __syncthreads();

    for (int sub = 0; sub < NSUB; sub++) {
        if (sub) __syncthreads();
        #pragma unroll
        for (int i = 0; i < 16; i++) {
            int idx = t + i*64;
            int c  = idx >> 4;
            int k4 = (idx & 15) << 2;
            *(float4*)&As[c][k4] = *(const float4*)(base + (size_t)c*HW + sub*SUB + k4);
        }
        __syncthreads();

        u64 acc[8][4];
        #pragma unroll
        for (int i = 0; i < 8; i++)
            #pragma unroll
            for (int j = 0; j < 4; j++) acc[i][j] = 0ULL;

        #pragma unroll 4
        for (int d = 0; d < DD; d++) {
            float4 a0 = *(const float4*)&Pt[d][r0];
            float4 a1 = *(const float4*)&Pt[d][r0+4];
            const u64* bp = (const u64*)&As[d][c0];
            u64 b0 = bp[0], b1 = bp[1], b2v = bp[2], b3 = bp[3];
            float av[8] = {a0.x,a0.y,a0.z,a0.w,a1.x,a1.y,a1.z,a1.w};
            #pragma unroll
            for (int ri = 0; ri < 8; ri++) {
                u64 a2 = pack2(av[ri], av[ri]);
                fma2(acc[ri][0], a2, b0);
                fma2(acc[ri][1], a2, b1);
                fma2(acc[ri][2], a2, b2v);
                fma2(acc[ri][3], a2, b3);
            }
        }

        // epilogue: add reweight branch, store from registers
        #pragma unroll
        for (int ri = 0; ri < 8; ri++) {
            int r = r0 + ri;
            float4 x0 = *(const float4*)&As[r][c0];
            float4 x1 = *(const float4*)&As[r][c0+4];
            float4 o0, o1;
            unpack2(acc[ri][0], o0.x, o0.y);
            unpack2(acc[ri][1], o0.z, o0.w);
            unpack2(acc[ri][2], o1.x, o1.y);
            unpack2(acc[ri][3], o1.z, o1.w);
            o0.x += coef[ri]*x0.x; o0.y += coef[ri]*x0.y;
            o0.z += coef[ri]*x0.z; o0.w += coef[ri]*x0.w;
            o1.x += coef[ri]*x1.x; o1.y += coef[ri]*x1.y;
            o1.z += coef[ri]*x1.z; o1.w += coef[ri]*x1.w;
            *(float4*)(obase + (size_t)r*HW + sub*SUB + c0)     = o0;
            *(float4*)(obase + (size_t)r*HW + sub*SUB + c0 + 4) = o1;
        }
    }
}

// ---------------------------------------------------------------------------
extern "C" void kernel_launch(void* const* d_in, const int* in_sizes, int n_in,
                              void* d_out, int out_size) {
    const float* X   = (const float*)d_in[0];
    const float* fc1 = (const float*)d_in[1];
    const float* lng = (const float*)d_in[2];
    const float* lnb = (const float*)d_in[3];
    const float* fc2 = (const float*)d_in[4];
    const float* xw  = (const float*)d_in[5];
    float* out = (float*)d_out;

    k_zero<<<64, 256>>>();
    dim3 grid(CHUNKS, GG, NB);
    k_statsgram<<<grid, 64>>>(X);
    k_reweight<<<NB, 256>>>(fc1, lng, lnb, fc2);
    k_sigma<<<GG, 256>>>();
    k_ns<<<GG, 256>>>(xw);
    k_apply<<<grid, 64>>>(X, xw, out);
}

// round 5
// speedup vs baseline: 1.4586x; 1.4586x over previous
#include <cuda_runtime.h>
#include <math.h>

// Problem constants
#define NB 32          // batch
#define CC 256         // channels
#define HW 4096        // H*W
#define GG 4           // groups
#define DD 64          // channels per group
#define MMTOT 131072   // m = NB*HW
#define CHUNKS 4       // hw chunks per (n,g)
#define TK 1024        // hw per chunk
#define SUB 64         // k-subtile
#define NSUB 16        // TK/SUB
#define LDA 68         // smem stride, gram tile  (bank = 4*row + k : conflict-free frags)
#define LDB 72         // smem stride, apply tile (bank = 8*k + n  : conflict-free frags)

// Scratch (device globals; no allocation allowed)
__device__ float g_sum[NB*CC];
__device__ float g_sumsq[NB*CC];
__device__ float g_gram[GG*DD*DD];
__device__ float g_sigman[GG*DD*DD];
__device__ float g_pw[GG*DD*DD];     // w * P per group
__device__ float g_y[NB*CC];         // sigmoid MLP output
__device__ float g_varsum;           // sum of x_var over all (n,c)

// ---------------------------------------------------------------------------
__device__ __forceinline__ unsigned f2tf(float x) {
    unsigned r; asm("cvt.rna.tf32.f32 %0, %1;" : "=r"(r) : "f"(x)); return r;
}

// m16n8k8 tf32 mma, accumulate in-place.
__device__ __forceinline__ void mma8(float c[4],
        unsigned a0, unsigned a1, unsigned a2, unsigned a3,
        unsigned b0, unsigned b1) {
    asm("mma.sync.aligned.m16n8k8.row.col.f32.tf32.tf32.f32 "
        "{%0,%1,%2,%3}, {%4,%5,%6,%7}, {%8,%9}, {%0,%1,%2,%3};"
        : "+f"(c[0]), "+f"(c[1]), "+f"(c[2]), "+f"(c[3])
        : "r"(a0), "r"(a1), "r"(a2), "r"(a3), "r"(b0), "r"(b1));
}

// ---------------------------------------------------------------------------
__global__ void k_zero() {
    int i = blockIdx.x * blockDim.x + threadIdx.x;
    if (i < NB*CC) { g_sum[i] = 0.f; g_sumsq[i] = 0.f; }
    if (i < GG*DD*DD) g_gram[i] = 0.f;
    if (i == 0) g_varsum = 0.f;
}

// ---------------------------------------------------------------------------
// Pass 1: read X once. Per-(n,c) sum & sumsq + per-group uncentered Gram
// via split-tf32 tensor-core mma. Grid: (CHUNKS, GG, NB), 256 threads.
// Gram[m][n] = sum_hw A[m][hw]*A[n][hw]  (contraction over contiguous hw).
__global__ __launch_bounds__(256, 2) void k_statsgram(const float* __restrict__ X) {
    __shared__ float Ah[DD*LDA];
    __shared__ float Al[DD*LDA];
    int n = blockIdx.z, g = blockIdx.y, chn = blockIdx.x;
    const float* base = X + ((size_t)(n*CC + g*DD))*HW + (size_t)chn*TK;
    int t = threadIdx.x, lane = t & 31, w = t >> 5;
    int gid = lane >> 2, tig = lane & 3;
    int m0 = (w & 3) << 4;      // warp row tile (16)
    int n0 = (w >> 2) << 5;     // warp col tile (32)

    float acc[4][4];
    #pragma unroll
    for (int j = 0; j < 4; j++)
        #pragma unroll
        for (int q = 0; q < 4; q++) acc[j][q] = 0.f;
    float s1[4] = {0.f,0.f,0.f,0.f}, s2[4] = {0.f,0.f,0.f,0.f};

    for (int sub = 0; sub < NSUB; sub++) {
        if (sub) __syncthreads();
        // load 64ch x 64hw tile, compute stats, split into tf32 hi/lo
        #pragma unroll
        for (int i = 0; i < 4; i++) {
            int idx = t + (i << 8);
            int c = idx >> 4, k4 = (idx & 15) << 2;
            float4 v = *(const float4*)(base + (size_t)c*HW + sub*SUB + k4);
            s1[i] += v.x + v.y + v.z + v.w;
            s2[i] += v.x*v.x + v.y*v.y + v.z*v.z + v.w*v.w;
            float hx = __uint_as_float(f2tf(v.x));
            float hy = __uint_as_float(f2tf(v.y));
            float hz = __uint_as_float(f2tf(v.z));
            float hw2 = __uint_as_float(f2tf(v.w));
            *(float4*)&Ah[c*LDA + k4] = make_float4(hx, hy, hz, hw2);
            *(float4*)&Al[c*LDA + k4] = make_float4(v.x-hx, v.y-hy, v.z-hz, v.w-hw2);
        }
        __syncthreads();

        #pragma unroll
        for (int k0 = 0; k0 < SUB; k0 += 8) {
            int ra = (m0 + gid)*LDA + k0 + tig;
            unsigned ah0 = __float_as_uint(Ah[ra]);
            unsigned ah1 = __float_as_uint(Ah[ra + 8*LDA]);
            unsigned ah2 = __float_as_uint(Ah[ra + 4]);
            unsigned ah3 = __float_as_uint(Ah[ra + 8*LDA + 4]);
            unsigned al0 = __float_as_uint(Al[ra]);
            unsigned al1 = __float_as_uint(Al[ra + 8*LDA]);
            unsigned al2 = __float_as_uint(Al[ra + 4]);
            unsigned al3 = __float_as_uint(Al[ra + 8*LDA + 4]);
            #pragma unroll
            for (int j = 0; j < 4; j++) {
                int rb = (n0 + 8*j + gid)*LDA + k0 + tig;
                unsigned bh0 = __float_as_uint(Ah[rb]);
                unsigned bh1 = __float_as_uint(Ah[rb + 4]);
                unsigned bl0 = __float_as_uint(Al[rb]);
                unsigned bl1 = __float_as_uint(Al[rb + 4]);
                mma8(acc[j], ah0, ah1, ah2, ah3, bh0, bh1);  // hi*hi
                mma8(acc[j], al0, al1, al2, al3, bh0, bh1);  // lo*hi
                mma8(acc[j], ah0, ah1, ah2, ah3, bl0, bl1);  // hi*lo
            }
        }
    }

    // per-channel stats: 16 threads share channel c = (t>>4) + 16*i
    #pragma unroll
    for (int i = 0; i < 4; i++) {
        float a = s1[i], b = s2[i];
        #pragma unroll
        for (int off = 8; off >= 1; off >>= 1) {
            a += __shfl_xor_sync(0xffffffffu, a, off, 16);
            b += __shfl_xor_sync(0xffffffffu, b, off, 16);
        }
        if ((t & 15) == 0) {
            int c = (t >> 4) + (i << 4);
            atomicAdd(&g_sum[n*CC + g*DD + c],   a);
            atomicAdd(&g_sumsq[n*CC + g*DD + c], b);
        }
    }
    // Gram accumulation (C frag layout: rows gid/gid+8, cols 2*tig, 2*tig+1)
    float* gg = &g_gram[g*DD*DD];
    #pragma unroll
    for (int j = 0; j < 4; j++) {
        int col = n0 + 8*j + 2*tig;
        atomicAdd(&gg[(m0+gid)*DD   + col],     acc[j][0]);
        atomicAdd(&gg[(m0+gid)*DD   + col + 1], acc[j][1]);
        atomicAdd(&gg[(m0+gid+8)*DD + col],     acc[j][2]);
        atomicAdd(&gg[(m0+gid+8)*DD + col + 1], acc[j][3]);
    }
}

// ---------------------------------------------------------------------------
// Per-n MLP: x_var -> fc1 -> LayerNorm -> relu -> fc2 -> sigmoid = y
__global__ __launch_bounds__(256) void k_reweight(const float* __restrict__ fc1,
                                                  const float* __restrict__ lng,
                                                  const float* __restrict__ lnb,
                                                  const float* __restrict__ fc2) {
    __shared__ float sv[CC];
    __shared__ float sh[DD];
    __shared__ float warpsum[8];
    __shared__ float sred[2];
    int n = blockIdx.x, t = threadIdx.x;

    float s  = g_sum[n*CC + t];
    float ss = g_sumsq[n*CC + t];
    float var = (ss - s*s*(1.0f/HW)) * (1.0f/(HW - 1));   // ddof=1
    sv[t] = var;

    float vs = var;
    #pragma unroll
    for (int o = 16; o; o >>= 1) vs += __shfl_xor_sync(0xffffffffu, vs, o);
    if ((t & 31) == 0) warpsum[t >> 5] = vs;
    __syncthreads();
    if (t == 0) {
        float tot = 0.f;
        #pragma unroll
        for (int i = 0; i < 8; i++) tot += warpsum[i];
        atomicAdd(&g_varsum, tot);
    }

    int w = t >> 5, l = t & 31;
    for (int kk = 0; kk < 8; kk++) {
        int k = w*8 + kk;
        float acc = 0.f;
        for (int c = l; c < CC; c += 32) acc += sv[c] * fc1[k*CC + c];
        #pragma unroll
        for (int o = 16; o; o >>= 1) acc += __shfl_xor_sync(0xffffffffu, acc, o);
        if (l == 0) sh[k] = acc;
    }
    __syncthreads();

    if (w == 0) {
        float h1 = sh[l], h2 = sh[l + 32];
        float su = h1 + h2, q = h1*h1 + h2*h2;
        #pragma unroll
        for (int o = 16; o; o >>= 1) {
            su += __shfl_xor_sync(0xffffffffu, su, o);
            q  += __shfl_xor_sync(0xffffffffu, q,  o);
        }
        float mu = su * (1.0f/DD);
        float vr = q * (1.0f/DD) - mu*mu;
        if (l == 0) { sred[0] = mu; sred[1] = rsqrtf(vr + 1e-5f); }
    }
    __syncthreads();
    float mu = sred[0], rstd = sred[1];
    if (t < DD) {
        float hh = (sh[t] - mu) * rstd * lng[t] + lnb[t];
        sh[t] = fmaxf(hh, 0.f);
    }
    __syncthreads();

    float acc = 0.f;
    #pragma unroll 8
    for (int k = 0; k < DD; k++) acc += sh[k] * fc2[t*DD + k];
    g_y[n*CC + t] = 1.0f / (1.0f + expf(-acc));
}

// ---------------------------------------------------------------------------
// Sigma_N per group
__global__ __launch_bounds__(256) void k_sigma() {
    int g = blockIdx.x, t = threadIdx.x;
    __shared__ float smean[DD];
    __shared__ float sS[DD*DD];
    __shared__ float strace;
    if (t < DD) {
        float s = 0.f;
        #pragma unroll 8
        for (int n = 0; n < NB; n++) s += g_sum[n*CC + g*DD + t];
        smean[t] = s * (1.0f/(float)MMTOT);
    }
    if (t == 0) strace = 0.f;
    __syncthreads();
    float tr = 0.f;
    #pragma unroll
    for (int i = 0; i < 16; i++) {
        int idx = t + i*256;
        int r = idx >> 6, c = idx & 63;
        float v = 1e-5f * (g_gram[g*DD*DD + idx] - (float)MMTOT * smean[r] * smean[c]);
        if (r == c) { v += 1.0f/(float)MMTOT; tr += v; }
        sS[idx] = v;
    }
    #pragma unroll
    for (int o = 16; o; o >>= 1) tr += __shfl_xor_sync(0xffffffffu, tr, o);
    if ((t & 31) == 0) atomicAdd(&strace, tr);
    __syncthreads();
    float rtr = 1.0f / strace;
    #pragma unroll
    for (int i = 0; i < 16; i++) {
        int idx = t + i*256;
        g_sigman[g*DD*DD + idx] = sS[idx] * rtr;
    }
}

// ---------------------------------------------------------------------------
// Newton-Schulz (T=3): P = -0.5 P + 1.5 (P@P@P@Sigma_N). One block per group.
__device__ __forceinline__ void mm_acc(float acc[4][4], const float* A,
                                       const float* B, int tx, int ty) {
    #pragma unroll
    for (int i = 0; i < 4; i++)
        #pragma unroll
        for (int j = 0; j < 4; j++) acc[i][j] = 0.f;
    #pragma unroll 8
    for (int k = 0; k < DD; k++) {
        float a[4];
        #pragma unroll
        for (int ri = 0; ri < 4; ri++) a[ri] = A[((ty<<2)+ri)*DD + k];
        float4 bv = *(const float4*)&B[k*DD + (tx<<2)];
        float b[4] = {bv.x, bv.y, bv.z, bv.w};
        #pragma unroll
        for (int ri = 0; ri < 4; ri++)
            #pragma unroll
            for (int cj = 0; cj < 4; cj++)
                acc[ri][cj] += a[ri]*b[cj];
    }
}

__global__ __launch_bounds__(256) void k_ns(const float* __restrict__ xw) {
    __shared__ float sm[3*DD*DD];
    float* sP = sm;
    float* sS = sm + DD*DD;
    float* sT = sm + 2*DD*DD;
    int g = blockIdx.x, t = threadIdx.x;
    int tx = t & 15, ty = t >> 4;

    #pragma unroll
    for (int i = 0; i < 16; i++) {
        int idx = t + i*256;
        sS[idx] = g_sigman[g*DD*DD + idx];
        sP[idx] = ((idx >> 6) == (idx & 63)) ? 1.0f : 0.0f;
    }
    __syncthreads();

    for (int it = 0; it < 3; it++) {
        float t1[4][4];
        mm_acc(t1, sP, sP, tx, ty);                 // T = P@P
        #pragma unroll
        for (int ri = 0; ri < 4; ri++)
            #pragma unroll
            for (int cj = 0; cj < 4; cj++)
                sT[((ty<<2)+ri)*DD + (tx<<2)+cj] = t1[ri][cj];
        __syncthreads();

        float p3[4][4];
        mm_acc(p3, sT, sP, tx, ty);                 // P^3 = T@P (regs)
        float pold[4][4];
        #pragma unroll
        for (int ri = 0; ri < 4; ri++)
            #pragma unroll
            for (int cj = 0; cj < 4; cj++)
                pold[ri][cj] = sP[((ty<<2)+ri)*DD + (tx<<2)+cj];
        __syncthreads();
        #pragma unroll
        for (int ri = 0; ri < 4; ri++)
            #pragma unroll
            for (int cj = 0; cj < 4; cj++)
                sP[((ty<<2)+ri)*DD + (tx<<2)+cj] = p3[ri][cj];
        __syncthreads();

        float f[4][4];
        mm_acc(f, sP, sS, tx, ty);                  // P^3 @ Sigma_N
        __syncthreads();
        #pragma unroll
        for (int ri = 0; ri < 4; ri++)
            #pragma unroll
            for (int cj = 0; cj < 4; cj++)
                sP[((ty<<2)+ri)*DD + (tx<<2)+cj] =
                    -0.5f*pold[ri][cj] + 1.5f*f[ri][cj];
        __syncthreads();
    }

    float w = 1.0f / (1.0f + expf(-xw[0]));
    #pragma unroll
    for (int i = 0; i < 16; i++) {
        int idx = t + i*256;
        g_pw[g*DD*DD + idx] = w * sP[idx];
    }
}

// ---------------------------------------------------------------------------
// Pass 2: out = wP@X + coef.*X via split-tf32 mma. P fragments in registers.
// Grid: (CHUNKS, GG, NB), 256 threads.
__global__ __launch_bounds__(256, 2) void k_apply(const float* __restrict__ X,
                                                  const float* __restrict__ xw,
                                                  float* __restrict__ out) {
    __shared__ float Xh[DD*LDB];
    __shared__ float Xl[DD*LDB];
    int n = blockIdx.z, g = blockIdx.y, chn = blockIdx.x;
    const float* base = X   + ((size_t)(n*CC + g*DD))*HW + (size_t)chn*TK;
    float*      obase = out + ((size_t)(n*CC + g*DD))*HW + (size_t)chn*TK;
    int t = threadIdx.x, lane = t & 31, w = t >> 5;
    int gid = lane >> 2, tig = lane & 3;
    int m0 = (w & 3) << 4;
    int nw0 = (w >> 2) << 5;

    // preload wP fragments (hi/lo) into registers: rows m0+gid(+8), k-tiles 0..7
    unsigned pah[8][4], pal[8][4];
    const float* P = &g_pw[g*DD*DD];
    #pragma unroll
    for (int kt = 0; kt < 8; kt++) {
        int k0 = kt*8;
        float v0 = P[(m0+gid)*DD   + k0 + tig];
        float v1 = P[(m0+gid+8)*DD + k0 + tig];
        float v2 = P[(m0+gid)*DD   + k0 + tig + 4];
        float v3 = P[(m0+gid+8)*DD + k0 + tig + 4];
        pah[kt][0] = f2tf(v0); pal[kt][0] = __float_as_uint(v0 - __uint_as_float(pah[kt][0]));
        pah[kt][1] = f2tf(v1); pal[kt][1] = __float_as_uint(v1 - __uint_as_float(pah[kt][1]));
        pah[kt][2] = f2tf(v2); pal[kt][2] = __float_as_uint(v2 - __uint_as_float(pah[kt][2]));
        pah[kt][3] = f2tf(v3); pal[kt][3] = __float_as_uint(v3 - __uint_as_float(pah[kt][3]));
    }
    float wblend = 1.0f / (1.0f + expf(-xw[0]));
    float rscale = rsqrtf(g_varsum * (1.0f/(float)(NB*CC)));
    float coef0 = (1.0f - wblend) * g_y[n*CC + g*DD + m0 + gid]     * rscale;
    float coef1 = (1.0f - wblend) * g_y[n*CC + g*DD + m0 + gid + 8] * rscale;

    for (int sub = 0; sub < NSUB; sub++) {
        if (sub) __syncthreads();
        #pragma unroll
        for (int i = 0; i < 4; i++) {
            int idx = t + (i << 8);
            int c = idx >> 4, k4 = (idx & 15) << 2;
            float4 v = *(const float4*)(base + (size_t)c*HW + sub*SUB + k4);
            float hx = __uint_as_float(f2tf(v.x));
            float hy = __uint_as_float(f2tf(v.y));
            float hz = __uint_as_float(f2tf(v.z));
            float hw2 = __uint_as_float(f2tf(v.w));
            *(float4*)&Xh[c*LDB + k4] = make_float4(hx, hy, hz, hw2);
            *(float4*)&Xl[c*LDB + k4] = make_float4(v.x-hx, v.y-hy, v.z-hz, v.w-hw2);
        }
        __syncthreads();

        float acc[4][4];
        #pragma unroll
        for (int j = 0; j < 4; j++)
            #pragma unroll
            for (int q = 0; q < 4; q++) acc[j][q] = 0.f;

        #pragma unroll
        for (int kt = 0; kt < 8; kt++) {
            int k0 = kt*8;
            #pragma unroll
            for (int j = 0; j < 4; j++) {
                int rb = (k0 + tig)*LDB + nw0 + 8*j + gid;
                unsigned bh0 = __float_as_uint(Xh[rb]);
                unsigned bh1 = __float_as_uint(Xh[rb + 4*LDB]);
                unsigned bl0 = __float_as_uint(Xl[rb]);
                unsigned bl1 = __float_as_uint(Xl[rb + 4*LDB]);
                mma8(acc[j], pah[kt][0], pah[kt][1], pah[kt][2], pah[kt][3], bh0, bh1);
                mma8(acc[j], pal[kt][0], pal[kt][1], pal[kt][2], pal[kt][3], bh0, bh1);
                mma8(acc[j], pah[kt][0], pah[kt][1], pah[kt][2], pah[kt][3], bl0, bl1);
            }
        }

        // epilogue: residual uses exact X = Xh + Xl
        #pragma unroll
        for (int j = 0; j < 4; j++) {
            int col = nw0 + 8*j + 2*tig;
            int r1 = m0 + gid, r2 = r1 + 8;
            float x10 = Xh[r1*LDB + col]     + Xl[r1*LDB + col];
            float x11 = Xh[r1*LDB + col + 1] + Xl[r1*LDB + col + 1];
            float x20 = Xh[r2*LDB + col]     + Xl[r2*LDB + col];
            float x21 = Xh[r2*LDB + col + 1] + Xl[r2*LDB + col + 1];
            float2 o1 = make_float2(acc[j][0] + coef0*x10, acc[j][1] + coef0*x11);
            float2 o2 = make_float2(acc[j][2] + coef1*x20, acc[j][3] + coef1*x21);
            *(float2*)(obase + (size_t)r1*HW + sub*SUB + col) = o1;
            *(float2*)(obase + (size_t)r2*HW + sub*SUB + col) = o2;
        }
    }
}

// ---------------------------------------------------------------------------
extern "C" void kernel_launch(void* const* d_in, const int* in_sizes, int n_in,
                              void* d_out, int out_size) {
    const float* X   = (const float*)d_in[0];
    const float* fc1 = (const float*)d_in[1];
    const float* lng = (const float*)d_in[2];
    const float* lnb = (const float*)d_in[3];
    const float* fc2 = (const float*)d_in[4];
    const float* xw  = (const float*)d_in[5];
    float* out = (float*)d_out;

    k_zero<<<64, 256>>>();
    dim3 grid(CHUNKS, GG, NB);
    k_statsgram<<<grid, 256>>>(X);
    k_reweight<<<NB, 256>>>(fc1, lng, lnb, fc2);
    k_sigma<<<GG, 256>>>();
    k_ns<<<GG, 256>>>(xw);
    k_apply<<<grid, 256>>>(X, xw, out);
}

// round 9
// speedup vs baseline: 1.6653x; 1.1417x over previous
#include <cuda_runtime.h>
#include <math.h>

// Problem constants
#define NB 32          // batch
#define CC 256         // channels
#define HW 4096        // H*W
#define GG 4           // groups
#define DD 64          // channels per group
#define MMTOT 131072   // m = NB*HW
#define CHUNKS 4       // hw chunks per (n,g)
#define TK 1024        // hw per chunk
#define SUB 64         // k-subtile
#define NSUB 16        // TK/SUB
#define LDA 68         // smem stride, gram tile  (bank = 4*row + k : conflict-free frags)
#define LDB 72         // smem stride, apply tile (bank = 8*k + n  : conflict-free frags)

// Scratch (device globals; no allocation allowed)
__device__ float g_sum[NB*CC];
__device__ float g_sumsq[NB*CC];
__device__ float g_gram[GG*DD*DD];
__device__ float g_pw[GG*DD*DD];     // w * P per group
__device__ float g_y[NB*CC];         // sigmoid MLP output
__device__ float g_varsum;           // sum of x_var over all (n,c)

// ---------------------------------------------------------------------------
__device__ __forceinline__ unsigned f2tf(float x) {
    unsigned r; asm("cvt.rna.tf32.f32 %0, %1;" : "=r"(r) : "f"(x)); return r;
}

// m16n8k8 tf32 mma, accumulate in-place.
__device__ __forceinline__ void mma8(float c[4],
        unsigned a0, unsigned a1, unsigned a2, unsigned a3,
        unsigned b0, unsigned b1) {
    asm("mma.sync.aligned.m16n8k8.row.col.f32.tf32.tf32.f32 "
        "{%0,%1,%2,%3}, {%4,%5,%6,%7}, {%8,%9}, {%0,%1,%2,%3};"
        : "+f"(c[0]), "+f"(c[1]), "+f"(c[2]), "+f"(c[3])
        : "r"(a0), "r"(a1), "r"(a2), "r"(a3), "r"(b0), "r"(b1));
}

// ---------------------------------------------------------------------------
__global__ void k_zero() {
    int i = blockIdx.x * blockDim.x + threadIdx.x;
    if (i < NB*CC) { g_sum[i] = 0.f; g_sumsq[i] = 0.f; }
    if (i < GG*DD*DD) g_gram[i] = 0.f;
    if (i == 0) g_varsum = 0.f;
}

// ---------------------------------------------------------------------------
// Pass 1: read X once. Per-(n,c) sum & sumsq + per-group uncentered Gram.
// Raw fp32 tile in smem; tf32 hi/lo produced in registers on the fly.
// 2-mma split: Gram ~= Ahi*Ahi^T + Alo*Ahi^T. Grid: (CHUNKS, GG, NB).
__global__ __launch_bounds__(256, 3) void k_statsgram(const float* __restrict__ X) {
    __shared__ float As[DD*LDA];
    int n = blockIdx.z, g = blockIdx.y, chn = blockIdx.x;
    const float* base = X + ((size_t)(n*CC + g*DD))*HW + (size_t)chn*TK;
    int t = threadIdx.x, lane = t & 31, w = t >> 5;
    int gid = lane >> 2, tig = lane & 3;
    int m0 = (w & 3) << 4;      // warp row tile (16)
    int n0 = (w >> 2) << 5;     // warp col tile (32)

    float acc[4][4];
    #pragma unroll
    for (int j = 0; j < 4; j++)
        #pragma unroll
        for (int q = 0; q < 4; q++) acc[j][q] = 0.f;
    float s1[4] = {0.f,0.f,0.f,0.f}, s2[4] = {0.f,0.f,0.f,0.f};

    // prefetch subtile 0 into registers
    float4 v[4];
    #pragma unroll
    for (int i = 0; i < 4; i++) {
        int idx = t + (i << 8);
        int c = idx >> 4, k4 = (idx & 15) << 2;
        v[i] = *(const float4*)(base + (size_t)c*HW + k4);
    }

    for (int sub = 0; sub < NSUB; sub++) {
        if (sub) __syncthreads();
        // stats + raw store
        #pragma unroll
        for (int i = 0; i < 4; i++) {
            int idx = t + (i << 8);
            int c = idx >> 4, k4 = (idx & 15) << 2;
            s1[i] += v[i].x + v[i].y + v[i].z + v[i].w;
            s2[i] += v[i].x*v[i].x + v[i].y*v[i].y + v[i].z*v[i].z + v[i].w*v[i].w;
            *(float4*)&As[c*LDA + k4] = v[i];
        }
        __syncthreads();
        // prefetch next subtile (LDG latency hidden under the mma loop)
        if (sub + 1 < NSUB) {
            #pragma unroll
            for (int i = 0; i < 4; i++) {
                int idx = t + (i << 8);
                int c = idx >> 4, k4 = (idx & 15) << 2;
                v[i] = *(const float4*)(base + (size_t)c*HW + (sub+1)*SUB + k4);
            }
        }

        #pragma unroll
        for (int k0 = 0; k0 < SUB; k0 += 8) {
            int ra = (m0 + gid)*LDA + k0 + tig;
            float a0r = As[ra];
            float a1r = As[ra + 8*LDA];
            float a2r = As[ra + 4];
            float a3r = As[ra + 8*LDA + 4];
            unsigned ah0 = f2tf(a0r), ah1 = f2tf(a1r), ah2 = f2tf(a2r), ah3 = f2tf(a3r);
            unsigned al0 = __float_as_uint(a0r - __uint_as_float(ah0));
            unsigned al1 = __float_as_uint(a1r - __uint_as_float(ah1));
            unsigned al2 = __float_as_uint(a2r - __uint_as_float(ah2));
            unsigned al3 = __float_as_uint(a3r - __uint_as_float(ah3));
            #pragma unroll
            for (int j = 0; j < 4; j++) {
                int rb = (n0 + 8*j + gid)*LDA + k0 + tig;
                unsigned bh0 = f2tf(As[rb]);
                unsigned bh1 = f2tf(As[rb + 4]);
                mma8(acc[j], ah0, ah1, ah2, ah3, bh0, bh1);  // hi*hi
                mma8(acc[j], al0, al1, al2, al3, bh0, bh1);  // lo*hi
            }
        }
    }

    // per-channel stats: 16 threads share channel c = (t>>4) + 16*i
    #pragma unroll
    for (int i = 0; i < 4; i++) {
        float a = s1[i], b = s2[i];
        #pragma unroll
        for (int off = 8; off >= 1; off >>= 1) {
            a += __shfl_xor_sync(0xffffffffu, a, off, 16);
            b += __shfl_xor_sync(0xffffffffu, b, off, 16);
        }
        if ((t & 15) == 0) {
            int c = (t >> 4) + (i << 4);
            atomicAdd(&g_sum[n*CC + g*DD + c],   a);
            atomicAdd(&g_sumsq[n*CC + g*DD + c], b);
        }
    }
    // Gram accumulation (C frag layout: rows gid/gid+8, cols 2*tig, 2*tig+1)
    float* gg = &g_gram[g*DD*DD];
    #pragma unroll
    for (int j = 0; j < 4; j++) {
        int col = n0 + 8*j + 2*tig;
        atomicAdd(&gg[(m0+gid)*DD   + col],     acc[j][0]);
        atomicAdd(&gg[(m0+gid)*DD   + col + 1], acc[j][1]);
        atomicAdd(&gg[(m0+gid+8)*DD + col],     acc[j][2]);
        atomicAdd(&gg[(m0+gid+8)*DD + col + 1], acc[j][3]);
    }
}

// ---------------------------------------------------------------------------
// Per-n MLP: x_var -> fc1 -> LayerNorm -> relu -> fc2 -> sigmoid = y
__global__ __launch_bounds__(256) void k_reweight(const float* __restrict__ fc1,
                                                  const float* __restrict__ lng,
                                                  const float* __restrict__ lnb,
                                                  const float* __restrict__ fc2) {
    __shared__ float sv[CC];
    __shared__ float sh[DD];
    __shared__ float warpsum[8];
    __shared__ float sred[2];
    int n = blockIdx.x, t = threadIdx.x;

    float s  = g_sum[n*CC + t];
    float ss = g_sumsq[n*CC + t];
    float var = (ss - s*s*(1.0f/HW)) * (1.0f/(HW - 1));   // ddof=1
    sv[t] = var;

    float vs = var;
    #pragma unroll
    for (int o = 16; o; o >>= 1) vs += __shfl_xor_sync(0xffffffffu, vs, o);
    if ((t & 31) == 0) warpsum[t >> 5] = vs;
    __syncthreads();
    if (t == 0) {
        float tot = 0.f;
        #pragma unroll
        for (int i = 0; i < 8; i++) tot += warpsum[i];
        atomicAdd(&g_varsum, tot);
    }

    int w = t >> 5, l = t & 31;
    for (int kk = 0; kk < 8; kk++) {
        int k = w*8 + kk;
        float acc = 0.f;
        for (int c = l; c < CC; c += 32) acc += sv[c] * fc1[k*CC + c];
        #pragma unroll
        for (int o = 16; o; o >>= 1) acc += __shfl_xor_sync(0xffffffffu, acc, o);
        if (l == 0) sh[k] = acc;
    }
    __syncthreads();

    if (w == 0) {
        float h1 = sh[l], h2 = sh[l + 32];
        float su = h1 + h2, q = h1*h1 + h2*h2;
        #pragma unroll
        for (int o = 16; o; o >>= 1) {
            su += __shfl_xor_sync(0xffffffffu, su, o);
            q  += __shfl_xor_sync(0xffffffffu, q,  o);
        }
        float mu = su * (1.0f/DD);
        float vr = q * (1.0f/DD) - mu*mu;
        if (l == 0) { sred[0] = mu; sred[1] = rsqrtf(vr + 1e-5f); }
    }
    __syncthreads();
    float mu = sred[0], rstd = sred[1];
    if (t < DD) {
        float hh = (sh[t] - mu) * rstd * lng[t] + lnb[t];
        sh[t] = fmaxf(hh, 0.f);
    }
    __syncthreads();

    float acc = 0.f;
    #pragma unroll 8
    for (int k = 0; k < DD; k++) acc += sh[k] * fc2[t*DD + k];
    g_y[n*CC + t] = 1.0f / (1.0f + expf(-acc));
}

// ---------------------------------------------------------------------------
// Fused Sigma_N + Newton-Schulz (T=3). One block per group.
// Sigma = (1/m)I + EPS*(Gram - m*mu*mu^T); Sigma_N = Sigma/trace(Sigma).
// Then P = -0.5 P + 1.5 (P@P@P@Sigma_N), 3 iterations. Writes w*P.
__device__ __forceinline__ void mm_acc(float acc[4][4], const float* A,
                                       const float* B, int tx, int ty) {
    #pragma unroll
    for (int i = 0; i < 4; i++)
        #pragma unroll
        for (int j = 0; j < 4; j++) acc[i][j] = 0.f;
    #pragma unroll 8
    for (int k = 0; k < DD; k++) {
        float a[4];
        #pragma unroll
        for (int ri = 0; ri < 4; ri++) a[ri] = A[((ty<<2)+ri)*DD + k];
        float4 bv = *(const float4*)&B[k*DD + (tx<<2)];
        float b[4] = {bv.x, bv.y, bv.z, bv.w};
        #pragma unroll
        for (int ri = 0; ri < 4; ri++)
            #pragma unroll
            for (int cj = 0; cj < 4; cj++)
                acc[ri][cj] += a[ri]*b[cj];
    }
}

__global__ __launch_bounds__(256) void k_ns(const float* __restrict__ xw) {
    __shared__ float sm[3*DD*DD];
    __shared__ float smean[DD];
    __shared__ float strace;
    float* sP = sm;
    float* sS = sm + DD*DD;
    float* sT = sm + 2*DD*DD;
    int g = blockIdx.x, t = threadIdx.x;
    int tx = t & 15, ty = t >> 4;

    // ---- build Sigma_N in smem ----
    if (t < DD) {
        float s = 0.f;
        #pragma unroll 8
        for (int n = 0; n < NB; n++) s += g_sum[n*CC + g*DD + t];
        smean[t] = s * (1.0f/(float)MMTOT);
    }
    if (t == 0) strace = 0.f;
    __syncthreads();
    float tr = 0.f;
    #pragma unroll
    for (int i = 0; i < 16; i++) {
        int idx = t + i*256;
        int r = idx >> 6, c = idx & 63;
        float vv = 1e-5f * (g_gram[g*DD*DD + idx] - (float)MMTOT * smean[r] * smean[c]);
        if (r == c) { vv += 1.0f/(float)MMTOT; tr += vv; }
        sS[idx] = vv;
        sP[idx] = (r == c) ? 1.0f : 0.0f;
    }
    #pragma unroll
    for (int o = 16; o; o >>= 1) tr += __shfl_xor_sync(0xffffffffu, tr, o);
    if ((t & 31) == 0) atomicAdd(&strace, tr);
    __syncthreads();
    float rtr = 1.0f / strace;
    #pragma unroll
    for (int i = 0; i < 16; i++) sS[t + i*256] *= rtr;
    __syncthreads();

    // ---- Newton-Schulz ----
    for (int it = 0; it < 3; it++) {
        float t1[4][4];
        mm_acc(t1, sP, sP, tx, ty);                 // T = P@P
        #pragma unroll
        for (int ri = 0; ri < 4; ri++)
            #pragma unroll
            for (int cj = 0; cj < 4; cj++)
                sT[((ty<<2)+ri)*DD + (tx<<2)+cj] = t1[ri][cj];
        __syncthreads();

        float p3[4][4];
        mm_acc(p3, sT, sP, tx, ty);                 // P^3 = T@P (regs)
        float pold[4][4];
        #pragma unroll
        for (int ri = 0; ri < 4; ri++)
            #pragma unroll
            for (int cj = 0; cj < 4; cj++)
                pold[ri][cj] = sP[((ty<<2)+ri)*DD + (tx<<2)+cj];
        __syncthreads();
        #pragma unroll
        for (int ri = 0; ri < 4; ri++)
            #pragma unroll
            for (int cj = 0; cj < 4; cj++)
                sP[((ty<<2)+ri)*DD + (tx<<2)+cj] = p3[ri][cj];
        __syncthreads();

        float f[4][4];
        mm_acc(f, sP, sS, tx, ty);                  // P^3 @ Sigma_N
        __syncthreads();
        #pragma unroll
        for (int ri = 0; ri < 4; ri++)
            #pragma unroll
            for (int cj = 0; cj < 4; cj++)
                sP[((ty<<2)+ri)*DD + (tx<<2)+cj] =
                    -0.5f*pold[ri][cj] + 1.5f*f[ri][cj];
        __syncthreads();
    }

    float w = 1.0f / (1.0f + expf(-xw[0]));
    #pragma unroll
    for (int i = 0; i < 16; i++) {
        int idx = t + i*256;
        g_pw[g*DD*DD + idx] = w * sP[idx];
    }
}

// ---------------------------------------------------------------------------
// Pass 2: out = wP@X + coef.*X. P hi-fragments in registers; X raw in smem,
// tf32 hi/lo on the fly. 2-mma: Phi*Xhi + Phi*Xlo (= Phi*X exactly).
// Grid: (CHUNKS, GG, NB), 256 threads.
__global__ __launch_bounds__(256, 3) void k_apply(const float* __restrict__ X,
                                                  const float* __restrict__ xw,
                                                  float* __restrict__ out) {
    __shared__ float Xs[DD*LDB];
    int n = blockIdx.z, g = blockIdx.y, chn = blockIdx.x;
    const float* base = X   + ((size_t)(n*CC + g*DD))*HW + (size_t)chn*TK;
    float*      obase = out + ((size_t)(n*CC + g*DD))*HW + (size_t)chn*TK;
    int t = threadIdx.x, lane = t & 31, w = t >> 5;
    int gid = lane >> 2, tig = lane & 3;
    int m0 = (w & 3) << 4;
    int nw0 = (w >> 2) << 5;

    // preload wP hi fragments into registers (rows m0+gid/+8, k-tiles 0..7)
    unsigned pah[8][4];
    const float* P = &g_pw[g*DD*DD];
    #pragma unroll
    for (int kt = 0; kt < 8; kt++) {
        int k0 = kt*8;
        pah[kt][0] = f2tf(P[(m0+gid)*DD   + k0 + tig]);
        pah[kt][1] = f2tf(P[(m0+gid+8)*DD + k0 + tig]);
        pah[kt][2] = f2tf(P[(m0+gid)*DD   + k0 + tig + 4]);
        pah[kt][3] = f2tf(P[(m0+gid+8)*DD + k0 + tig + 4]);
    }
    float wblend = 1.0f / (1.0f + expf(-xw[0]));
    float rscale = rsqrtf(g_varsum * (1.0f/(float)(NB*CC)));
    float coef0 = (1.0f - wblend) * g_y[n*CC + g*DD + m0 + gid]     * rscale;
    float coef1 = (1.0f - wblend) * g_y[n*CC + g*DD + m0 + gid + 8] * rscale;

    // prefetch subtile 0
    float4 v[4];
    #pragma unroll
    for (int i = 0; i < 4; i++) {
        int idx = t + (i << 8);
        int c = idx >> 4, k4 = (idx & 15) << 2;
        v[i] = *(const float4*)(base + (size_t)c*HW + k4);
    }

    for (int sub = 0; sub < NSUB; sub++) {
        if (sub) __syncthreads();
        #pragma unroll
        for (int i = 0; i < 4; i++) {
            int idx = t + (i << 8);
            int c = idx >> 4, k4 = (idx & 15) << 2;
            *(float4*)&Xs[c*LDB + k4] = v[i];
        }
        __syncthreads();
        if (sub + 1 < NSUB) {
            #pragma unroll
            for (int i = 0; i < 4; i++) {
                int idx = t + (i << 8);
                int c = idx >> 4, k4 = (idx & 15) << 2;
                v[i] = *(const float4*)(base + (size_t)c*HW + (sub+1)*SUB + k4);
            }
        }

        float acc[4][4];
        #pragma unroll
        for (int j = 0; j < 4; j++)
            #pragma unroll
            for (int q = 0; q < 4; q++) acc[j][q] = 0.f;

        #pragma unroll
        for (int kt = 0; kt < 8; kt++) {
            int k0 = kt*8;
            #pragma unroll
            for (int j = 0; j < 4; j++) {
                int rb = (k0 + tig)*LDB + nw0 + 8*j + gid;
                float b0r = Xs[rb];
                float b1r = Xs[rb + 4*LDB];
                unsigned bh0 = f2tf(b0r), bh1 = f2tf(b1r);
                unsigned bl0 = __float_as_uint(b0r - __uint_as_float(bh0));
                unsigned bl1 = __float_as_uint(b1r - __uint_as_float(bh1));
                mma8(acc[j], pah[kt][0], pah[kt][1], pah[kt][2], pah[kt][3], bh0, bh1);
                mma8(acc[j], pah[kt][0], pah[kt][1], pah[kt][2], pah[kt][3], bl0, bl1);
            }
        }

        // epilogue: residual uses exact raw X
        #pragma unroll
        for (int j = 0; j < 4; j++) {
            int col = nw0 + 8*j + 2*tig;
            int r1 = m0 + gid, r2 = r1 + 8;
            float x10 = Xs[r1*LDB + col],     x11 = Xs[r1*LDB + col + 1];
            float x20 = Xs[r2*LDB + col],     x21 = Xs[r2*LDB + col + 1];
            float2 o1 = make_float2(acc[j][0] + coef0*x10, acc[j][1] + coef0*x11);
            float2 o2 = make_float2(acc[j][2] + coef1*x20, acc[j][3] + coef1*x21);
            *(float2*)(obase + (size_t)r1*HW + sub*SUB + col) = o1;
            *(float2*)(obase + (size_t)r2*HW + sub*SUB + col) = o2;
        }
    }
}

// ---------------------------------------------------------------------------
extern "C" void kernel_launch(void* const* d_in, const int* in_sizes, int n_in,
                              void* d_out, int out_size) {
    const float* X   = (const float*)d_in[0];
    const float* fc1 = (const float*)d_in[1];
    const float* lng = (const float*)d_in[2];
    const float* lnb = (const float*)d_in[3];
    const float* fc2 = (const float*)d_in[4];
    const float* xw  = (const float*)d_in[5];
    float* out = (float*)d_out;

    k_zero<<<64, 256>>>();
    dim3 grid(CHUNKS, GG, NB);
    k_statsgram<<<grid, 256>>>(X);
    k_reweight<<<NB, 256>>>(fc1, lng, lnb, fc2);
    k_ns<<<GG, 256>>>(xw);
    k_apply<<<grid, 256>>>(X, xw, out);
}

// round 12
// speedup vs baseline: 2.0059x; 1.2045x over previous
#include <cuda_runtime.h>
#include <math.h>

// Problem constants
#define NB 32          // batch
#define CC 256         // channels
#define HW 4096        // H*W
#define GG 4           // groups
#define DD 64          // channels per group
#define MMTOT 131072   // m = NB*HW
#define CHUNKS 4       // hw chunks per (n,g)
#define TK 1024        // hw per chunk
#define SUB 64         // k-subtile
#define NSUB 16        // TK/SUB
#define LDA 68         // smem stride, gram tile  (bank = 4*row + k : conflict-free frags)
#define LDB 72         // smem stride, apply tile (bank = 8*k + n  : conflict-free frags)

// XOR swizzle for the 64-stride NS matrices: phys(r,c) = r*64 + (c ^ ((r&7)<<2))
#define SW(r,c) (((r) << 6) + ((c) ^ (((r) & 7) << 2)))

// Scratch (device globals; no allocation allowed)
__device__ float g_sum[NB*CC];
__device__ float g_sumsq[NB*CC];
__device__ float g_gram[GG*DD*DD];
__device__ float g_pw[GG*DD*DD];     // w * P per group
__device__ float g_y[NB*CC];         // sigmoid MLP output
__device__ float g_varsum;           // sum of x_var over all (n,c)

// ---------------------------------------------------------------------------
__device__ __forceinline__ unsigned f2tf(float x) {
    unsigned r; asm("cvt.rna.tf32.f32 %0, %1;" : "=r"(r) : "f"(x)); return r;
}

// m16n8k8 tf32 mma, accumulate in-place.
__device__ __forceinline__ void mma8(float c[4],
        unsigned a0, unsigned a1, unsigned a2, unsigned a3,
        unsigned b0, unsigned b1) {
    asm("mma.sync.aligned.m16n8k8.row.col.f32.tf32.tf32.f32 "
        "{%0,%1,%2,%3}, {%4,%5,%6,%7}, {%8,%9}, {%0,%1,%2,%3};"
        : "+f"(c[0]), "+f"(c[1]), "+f"(c[2]), "+f"(c[3])
        : "r"(a0), "r"(a1), "r"(a2), "r"(a3), "r"(b0), "r"(b1));
}

// ---------------------------------------------------------------------------
__global__ void k_zero() {
    int i = blockIdx.x * blockDim.x + threadIdx.x;
    if (i < NB*CC) { g_sum[i] = 0.f; g_sumsq[i] = 0.f; }
    if (i < GG*DD*DD) g_gram[i] = 0.f;
    if (i == 0) g_varsum = 0.f;
}

// ---------------------------------------------------------------------------
// Pass 1: read X once. Per-(n,c) sum & sumsq + per-group uncentered Gram.
// Raw fp32 tile in smem; tf32 hi produced in registers on the fly.
// 1-mma: Gram ~= Ahi*Ahi^T. Grid: (CHUNKS, GG, NB).
__global__ __launch_bounds__(256, 3) void k_statsgram(const float* __restrict__ X) {
    __shared__ float As[DD*LDA];
    int n = blockIdx.z, g = blockIdx.y, chn = blockIdx.x;
    const float* base = X + ((size_t)(n*CC + g*DD))*HW + (size_t)chn*TK;
    int t = threadIdx.x, lane = t & 31, w = t >> 5;
    int gid = lane >> 2, tig = lane & 3;
    int m0 = (w & 3) << 4;      // warp row tile (16)
    int n0 = (w >> 2) << 5;     // warp col tile (32)

    float acc[4][4];
    #pragma unroll
    for (int j = 0; j < 4; j++)
        #pragma unroll
        for (int q = 0; q < 4; q++) acc[j][q] = 0.f;
    float s1[4] = {0.f,0.f,0.f,0.f}, s2[4] = {0.f,0.f,0.f,0.f};

    // prefetch subtile 0 into registers
    float4 v[4];
    #pragma unroll
    for (int i = 0; i < 4; i++) {
        int idx = t + (i << 8);
        int c = idx >> 4, k4 = (idx & 15) << 2;
        v[i] = *(const float4*)(base + (size_t)c*HW + k4);
    }

    for (int sub = 0; sub < NSUB; sub++) {
        if (sub) __syncthreads();
        #pragma unroll
        for (int i = 0; i < 4; i++) {
            int idx = t + (i << 8);
            int c = idx >> 4, k4 = (idx & 15) << 2;
            s1[i] += v[i].x + v[i].y + v[i].z + v[i].w;
            s2[i] += v[i].x*v[i].x + v[i].y*v[i].y + v[i].z*v[i].z + v[i].w*v[i].w;
            *(float4*)&As[c*LDA + k4] = v[i];
        }
        __syncthreads();
        if (sub + 1 < NSUB) {
            #pragma unroll
            for (int i = 0; i < 4; i++) {
                int idx = t + (i << 8);
                int c = idx >> 4, k4 = (idx & 15) << 2;
                v[i] = *(const float4*)(base + (size_t)c*HW + (sub+1)*SUB + k4);
            }
        }

        #pragma unroll
        for (int k0 = 0; k0 < SUB; k0 += 8) {
            int ra = (m0 + gid)*LDA + k0 + tig;
            unsigned ah0 = f2tf(As[ra]);
            unsigned ah1 = f2tf(As[ra + 8*LDA]);
            unsigned ah2 = f2tf(As[ra + 4]);
            unsigned ah3 = f2tf(As[ra + 8*LDA + 4]);
            #pragma unroll
            for (int j = 0; j < 4; j++) {
                int rb = (n0 + 8*j + gid)*LDA + k0 + tig;
                unsigned bh0 = f2tf(As[rb]);
                unsigned bh1 = f2tf(As[rb + 4]);
                mma8(acc[j], ah0, ah1, ah2, ah3, bh0, bh1);  // hi*hi only
            }
        }
    }

    // per-channel stats: 16 threads share channel c = (t>>4) + 16*i
    #pragma unroll
    for (int i = 0; i < 4; i++) {
        float a = s1[i], b = s2[i];
        #pragma unroll
        for (int off = 8; off >= 1; off >>= 1) {
            a += __shfl_xor_sync(0xffffffffu, a, off, 16);
            b += __shfl_xor_sync(0xffffffffu, b, off, 16);
        }
        if ((t & 15) == 0) {
            int c = (t >> 4) + (i << 4);
            atomicAdd(&g_sum[n*CC + g*DD + c],   a);
            atomicAdd(&g_sumsq[n*CC + g*DD + c], b);
        }
    }
    // Gram accumulation (C frag layout: rows gid/gid+8, cols 2*tig, 2*tig+1)
    float* gg = &g_gram[g*DD*DD];
    #pragma unroll
    for (int j = 0; j < 4; j++) {
        int col = n0 + 8*j + 2*tig;
        atomicAdd(&gg[(m0+gid)*DD   + col],     acc[j][0]);
        atomicAdd(&gg[(m0+gid)*DD   + col + 1], acc[j][1]);
        atomicAdd(&gg[(m0+gid+8)*DD + col],     acc[j][2]);
        atomicAdd(&gg[(m0+gid+8)*DD + col + 1], acc[j][3]);
    }
}

// ---------------------------------------------------------------------------
// Per-n MLP: x_var -> fc1 -> LayerNorm -> relu -> fc2 -> sigmoid = y
__global__ __launch_bounds__(256) void k_reweight(const float* __restrict__ fc1,
                                                  const float* __restrict__ lng,
                                                  const float* __restrict__ lnb,
                                                  const float* __restrict__ fc2) {
    __shared__ float sv[CC];
    __shared__ float sh[DD];
    __shared__ float warpsum[8];
    __shared__ float sred[2];
    int n = blockIdx.x, t = threadIdx.x;

    float s  = g_sum[n*CC + t];
    float ss = g_sumsq[n*CC + t];
    float var = (ss - s*s*(1.0f/HW)) * (1.0f/(HW - 1));   // ddof=1
    sv[t] = var;

    float vs = var;
    #pragma unroll
    for (int o = 16; o; o >>= 1) vs += __shfl_xor_sync(0xffffffffu, vs, o);
    if ((t & 31) == 0) warpsum[t >> 5] = vs;
    __syncthreads();
    if (t == 0) {
        float tot = 0.f;
        #pragma unroll
        for (int i = 0; i < 8; i++) tot += warpsum[i];
        atomicAdd(&g_varsum, tot);
    }

    int w = t >> 5, l = t & 31;
    for (int kk = 0; kk < 8; kk++) {
        int k = w*8 + kk;
        float acc = 0.f;
        for (int c = l; c < CC; c += 32) acc += sv[c] * fc1[k*CC + c];
        #pragma unroll
        for (int o = 16; o; o >>= 1) acc += __shfl_xor_sync(0xffffffffu, acc, o);
        if (l == 0) sh[k] = acc;
    }
    __syncthreads();

    if (w == 0) {
        float h1 = sh[l], h2 = sh[l + 32];
        float su = h1 + h2, q = h1*h1 + h2*h2;
        #pragma unroll
        for (int o = 16; o; o >>= 1) {
            su += __shfl_xor_sync(0xffffffffu, su, o);
            q  += __shfl_xor_sync(0xffffffffu, q,  o);
        }
        float mu = su * (1.0f/DD);
        float vr = q * (1.0f/DD) - mu*mu;
        if (l == 0) { sred[0] = mu; sred[1] = rsqrtf(vr + 1e-5f); }
    }
    __syncthreads();
    float mu = sred[0], rstd = sred[1];
    if (t < DD) {
        float hh = (sh[t] - mu) * rstd * lng[t] + lnb[t];
        sh[t] = fmaxf(hh, 0.f);
    }
    __syncthreads();

    float acc = 0.f;
    #pragma unroll 8
    for (int k = 0; k < DD; k++) acc += sh[k] * fc2[t*DD + k];
    g_y[n*CC + t] = 1.0f / (1.0f + expf(-acc));
}

// ---------------------------------------------------------------------------
// Fused Sigma_N + Newton-Schulz (T=3), tensor-core matmuls.
// All three 64x64 matrices live in XOR-swizzled 64-stride smem.
// One block (8 warps) per group.
__device__ __forceinline__ void mm_tc(float c[4][4], const float* __restrict__ A,
                                      const float* __restrict__ B,
                                      int m0, int n0, int gid, int tig) {
    #pragma unroll
    for (int j = 0; j < 4; j++)
        #pragma unroll
        for (int q = 0; q < 4; q++) c[j][q] = 0.f;
    #pragma unroll
    for (int k0 = 0; k0 < DD; k0 += 8) {
        float a0r = A[SW(m0+gid,   k0+tig)];
        float a1r = A[SW(m0+gid+8, k0+tig)];
        float a2r = A[SW(m0+gid,   k0+tig+4)];
        float a3r = A[SW(m0+gid+8, k0+tig+4)];
        unsigned ah0 = f2tf(a0r), ah1 = f2tf(a1r), ah2 = f2tf(a2r), ah3 = f2tf(a3r);
        unsigned al0 = __float_as_uint(a0r - __uint_as_float(ah0));
        unsigned al1 = __float_as_uint(a1r - __uint_as_float(ah1));
        unsigned al2 = __float_as_uint(a2r - __uint_as_float(ah2));
        unsigned al3 = __float_as_uint(a3r - __uint_as_float(ah3));
        #pragma unroll
        for (int j = 0; j < 4; j++) {
            unsigned bh0 = f2tf(B[SW(k0+tig,   n0+8*j+gid)]);
            unsigned bh1 = f2tf(B[SW(k0+tig+4, n0+8*j+gid)]);
            mma8(c[j], ah0, ah1, ah2, ah3, bh0, bh1);  // hi*hi
            mma8(c[j], al0, al1, al2, al3, bh0, bh1);  // lo*hi
        }
    }
}

__device__ __forceinline__ void st_tile(float* __restrict__ D, const float c[4][4],
                                        int m0, int n0, int gid, int tig) {
    #pragma unroll
    for (int j = 0; j < 4; j++) {
        int col = n0 + 8*j + 2*tig;
        D[SW(m0+gid,   col)]     = c[j][0];
        D[SW(m0+gid,   col + 1)] = c[j][1];
        D[SW(m0+gid+8, col)]     = c[j][2];
        D[SW(m0+gid+8, col + 1)] = c[j][3];
    }
}

__global__ __launch_bounds__(256) void k_ns(const float* __restrict__ xw) {
    __shared__ float sP[DD*DD];
    __shared__ float sS[DD*DD];
    __shared__ float sT[DD*DD];
    __shared__ float smean[DD];
    __shared__ float strace;
    int g = blockIdx.x, t = threadIdx.x;
    int lane = t & 31, w = t >> 5;
    int gid = lane >> 2, tig = lane & 3;
    int m0 = (w & 3) << 4;
    int n0 = (w >> 2) << 5;

    // ---- build Sigma_N (swizzled) ----
    if (t < DD) {
        float s = 0.f;
        #pragma unroll 8
        for (int n = 0; n < NB; n++) s += g_sum[n*CC + g*DD + t];
        smean[t] = s * (1.0f/(float)MMTOT);
    }
    if (t == 0) strace = 0.f;
    __syncthreads();
    float tr = 0.f;
    #pragma unroll
    for (int i = 0; i < 16; i++) {
        int idx = t + i*256;
        int r = idx >> 6, c = idx & 63;
        float vv = 1e-5f * (g_gram[g*DD*DD + idx] - (float)MMTOT * smean[r] * smean[c]);
        if (r == c) { vv += 1.0f/(float)MMTOT; tr += vv; }
        sS[SW(r,c)] = vv;
        sP[SW(r,c)] = (r == c) ? 1.0f : 0.0f;
    }
    #pragma unroll
    for (int o = 16; o; o >>= 1) tr += __shfl_xor_sync(0xffffffffu, tr, o);
    if ((t & 31) == 0) atomicAdd(&strace, tr);
    __syncthreads();
    float rtr = 1.0f / strace;
    #pragma unroll
    for (int i = 0; i < 16; i++) sS[t + i*256] *= rtr;   // layout-agnostic scale
    __syncthreads();

    // ---- Newton-Schulz, 3 iterations ----
    for (int it = 0; it < 3; it++) {
        float cr[4][4];
        mm_tc(cr, sP, sP, m0, n0, gid, tig);     // T = P@P
        st_tile(sT, cr, m0, n0, gid, tig);
        __syncthreads();                         // bar1: sT writes visible

        mm_tc(cr, sT, sP, m0, n0, gid, tig);     // P3 = T@P (regs)
        float pold[4][4];
        #pragma unroll
        for (int j = 0; j < 4; j++) {
            int col = n0 + 8*j + 2*tig;
            pold[j][0] = sP[SW(m0+gid,   col)];
            pold[j][1] = sP[SW(m0+gid,   col+1)];
            pold[j][2] = sP[SW(m0+gid+8, col)];
            pold[j][3] = sP[SW(m0+gid+8, col+1)];
        }
        __syncthreads();                         // bar2: sT reads done
        st_tile(sT, cr, m0, n0, gid, tig);       // sT <- P3
        __syncthreads();                         // bar3

        mm_tc(cr, sT, sS, m0, n0, gid, tig);     // F = P3@S
        #pragma unroll
        for (int j = 0; j < 4; j++)
            #pragma unroll
            for (int q = 0; q < 4; q++)
                cr[j][q] = -0.5f*pold[j][q] + 1.5f*cr[j][q];
        st_tile(sP, cr, m0, n0, gid, tig);       // P <- update
        __syncthreads();                         // bar4
    }

    float wb = 1.0f / (1.0f + expf(-xw[0]));
    #pragma unroll
    for (int i = 0; i < 16; i++) {
        int idx = t + i*256;
        int r = idx >> 6, c = idx & 63;
        g_pw[g*DD*DD + idx] = wb * sP[SW(r,c)];
    }
}

// ---------------------------------------------------------------------------
// Pass 2: out = wP@X + coef.*X. P hi-fragments in registers; X raw in smem,
// 1-mma: Phi@Xhi. Residual branch uses exact raw X. Grid: (CHUNKS, GG, NB).
__global__ __launch_bounds__(256, 3) void k_apply(const float* __restrict__ X,
                                                  const float* __restrict__ xw,
                                                  float* __restrict__ out) {
    __shared__ float Xs[DD*LDB];
    int n = blockIdx.z, g = blockIdx.y, chn = blockIdx.x;
    const float* base = X   + ((size_t)(n*CC + g*DD))*HW + (size_t)chn*TK;
    float*      obase = out + ((size_t)(n*CC + g*DD))*HW + (size_t)chn*TK;
    int t = threadIdx.x, lane = t & 31, w = t >> 5;
    int gid = lane >> 2, tig = lane & 3;
    int m0 = (w & 3) << 4;
    int nw0 = (w >> 2) << 5;

    // preload wP hi fragments into registers (rows m0+gid/+8, k-tiles 0..7)
    unsigned pah[8][4];
    const float* P = &g_pw[g*DD*DD];
    #pragma unroll
    for (int kt = 0; kt < 8; kt++) {
        int k0 = kt*8;
        pah[kt][0] = f2tf(P[(m0+gid)*DD   + k0 + tig]);
        pah[kt][1] = f2tf(P[(m0+gid+8)*DD + k0 + tig]);
        pah[kt][2] = f2tf(P[(m0+gid)*DD   + k0 + tig + 4]);
        pah[kt][3] = f2tf(P[(m0+gid+8)*DD + k0 + tig + 4]);
    }
    float wblend = 1.0f / (1.0f + expf(-xw[0]));
    float rscale = rsqrtf(g_varsum * (1.0f/(float)(NB*CC)));
    float coef0 = (1.0f - wblend) * g_y[n*CC + g*DD + m0 + gid]     * rscale;
    float coef1 = (1.0f - wblend) * g_y[n*CC + g*DD + m0 + gid + 8] * rscale;

    // prefetch subtile 0
    float4 v[4];
    #pragma unroll
    for (int i = 0; i < 4; i++) {
        int idx = t + (i << 8);
        int c = idx >> 4, k4 = (idx & 15) << 2;
        v[i] = *(const float4*)(base + (size_t)c*HW + k4);
    }

    for (int sub = 0; sub < NSUB; sub++) {
        if (sub) __syncthreads();
        #pragma unroll
        for (int i = 0; i < 4; i++) {
            int idx = t + (i << 8);
            int c = idx >> 4, k4 = (idx & 15) << 2;
            *(float4*)&Xs[c*LDB + k4] = v[i];
        }
        __syncthreads();
        if (sub + 1 < NSUB) {
            #pragma unroll
            for (int i = 0; i < 4; i++) {
                int idx = t + (i << 8);
                int c = idx >> 4, k4 = (idx & 15) << 2;
                v[i] = *(const float4*)(base + (size_t)c*HW + (sub+1)*SUB + k4);
            }
        }

        float acc[4][4];
        #pragma unroll
        for (int j = 0; j < 4; j++)
            #pragma unroll
            for (int q = 0; q < 4; q++) acc[j][q] = 0.f;

        #pragma unroll
        for (int kt = 0; kt < 8; kt++) {
            int k0 = kt*8;
            #pragma unroll
            for (int j = 0; j < 4; j++) {
                int rb = (k0 + tig)*LDB + nw0 + 8*j + gid;
                unsigned bh0 = f2tf(Xs[rb]);
                unsigned bh1 = f2tf(Xs[rb + 4*LDB]);
                mma8(acc[j], pah[kt][0], pah[kt][1], pah[kt][2], pah[kt][3], bh0, bh1);
            }
        }

        // epilogue: residual uses exact raw X
        #pragma unroll
        for (int j = 0; j < 4; j++) {
            int col = nw0 + 8*j + 2*tig;
            int r1 = m0 + gid, r2 = r1 + 8;
            float x10 = Xs[r1*LDB + col],     x11 = Xs[r1*LDB + col + 1];
            float x20 = Xs[r2*LDB + col],     x21 = Xs[r2*LDB + col + 1];
            float2 o1 = make_float2(acc[j][0] + coef0*x10, acc[j][1] + coef0*x11);
            float2 o2 = make_float2(acc[j][2] + coef1*x20, acc[j][3] + coef1*x21);
            *(float2*)(obase + (size_t)r1*HW + sub*SUB + col) = o1;
            *(float2*)(obase + (size_t)r2*HW + sub*SUB + col) = o2;
        }
    }
}

// ---------------------------------------------------------------------------
extern "C" void kernel_launch(void* const* d_in, const int* in_sizes, int n_in,
                              void* d_out, int out_size) {
    const float* X   = (const float*)d_in[0];
    const float* fc1 = (const float*)d_in[1];
    const float* lng = (const float*)d_in[2];
    const float* lnb = (const float*)d_in[3];
    const float* fc2 = (const float*)d_in[4];
    const float* xw  = (const float*)d_in[5];
    float* out = (float*)d_out;

    k_zero<<<64, 256>>>();
    dim3 grid(CHUNKS, GG, NB);
    k_statsgram<<<grid, 256>>>(X);
    k_reweight<<<NB, 256>>>(fc1, lng, lnb, fc2);
    k_ns<<<GG, 256>>>(xw);
    k_apply<<<grid, 256>>>(X, xw, out);
}

// round 13
// speedup vs baseline: 2.2568x; 1.1251x over previous
#include <cuda_runtime.h>
#include <math.h>

// Problem constants
#define NB 32          // batch
#define CC 256         // channels
#define HW 4096        // H*W
#define GG 4           // groups
#define DD 64          // channels per group
#define MMTOT 131072   // m = NB*HW
#define CHUNKS 4       // hw chunks per (n,g)
#define TK 1024        // hw per chunk
#define SUB 64         // k-subtile
#define NSUB 16        // TK/SUB
#define LDA 68         // smem stride, gram tile  (bank = 4*row + k : conflict-free frags)
#define LDB 72         // smem stride, apply tile (bank = 8*k + n  : conflict-free frags)

// XOR swizzle for the 64-stride NS matrices: phys(r,c) = r*64 + (c ^ ((r&7)<<2))
#define SW(r,c) (((r) << 6) + ((c) ^ (((r) & 7) << 2)))

// Scratch (device globals; no allocation allowed)
__device__ float g_sum[NB*CC];
__device__ float g_sumsq[NB*CC];
__device__ float g_gram[GG*DD*DD];
__device__ float g_pw[GG*DD*DD];     // w * P per group
__device__ float g_y[NB*CC];         // sigmoid MLP output
__device__ float g_varsum;           // sum of x_var over all (n,c)

// ---------------------------------------------------------------------------
__device__ __forceinline__ unsigned f2tf(float x) {
    unsigned r; asm("cvt.rna.tf32.f32 %0, %1;" : "=r"(r) : "f"(x)); return r;
}
__device__ __forceinline__ float f2tff(float x) {
    unsigned r; asm("cvt.rna.tf32.f32 %0, %1;" : "=r"(r) : "f"(x));
    return __uint_as_float(r);
}

// m16n8k8 tf32 mma, accumulate in-place.
__device__ __forceinline__ void mma8(float c[4],
        unsigned a0, unsigned a1, unsigned a2, unsigned a3,
        unsigned b0, unsigned b1) {
    asm("mma.sync.aligned.m16n8k8.row.col.f32.tf32.tf32.f32 "
        "{%0,%1,%2,%3}, {%4,%5,%6,%7}, {%8,%9}, {%0,%1,%2,%3};"
        : "+f"(c[0]), "+f"(c[1]), "+f"(c[2]), "+f"(c[3])
        : "r"(a0), "r"(a1), "r"(a2), "r"(a3), "r"(b0), "r"(b1));
}

// ---------------------------------------------------------------------------
__global__ void k_zero() {
    int i = blockIdx.x * blockDim.x + threadIdx.x;
    if (i < NB*CC) { g_sum[i] = 0.f; g_sumsq[i] = 0.f; }
    if (i < GG*DD*DD) g_gram[i] = 0.f;
    if (i == 0) g_varsum = 0.f;
}

// ---------------------------------------------------------------------------
// Pass 1: read X once. Per-(n,c) sum & sumsq (raw fp32) + per-group Gram
// (hi*hi^T). The smem tile holds tf32-PRE-ROUNDED values, so the mma
// fragment loads are plain LDS with no per-read cvt.
// Grid: (CHUNKS, GG, NB), 256 threads.
__global__ __launch_bounds__(256, 3) void k_statsgram(const float* __restrict__ X) {
    __shared__ float As[DD*LDA];
    int n = blockIdx.z, g = blockIdx.y, chn = blockIdx.x;
    const float* base = X + ((size_t)(n*CC + g*DD))*HW + (size_t)chn*TK;
    int t = threadIdx.x, lane = t & 31, w = t >> 5;
    int gid = lane >> 2, tig = lane & 3;
    int m0 = (w & 3) << 4;      // warp row tile (16)
    int n0 = (w >> 2) << 5;     // warp col tile (32)

    float acc[4][4];
    #pragma unroll
    for (int j = 0; j < 4; j++)
        #pragma unroll
        for (int q = 0; q < 4; q++) acc[j][q] = 0.f;
    float s1[4] = {0.f,0.f,0.f,0.f}, s2[4] = {0.f,0.f,0.f,0.f};

    // prefetch subtile 0 into registers
    float4 v[4];
    #pragma unroll
    for (int i = 0; i < 4; i++) {
        int idx = t + (i << 8);
        int c = idx >> 4, k4 = (idx & 15) << 2;
        v[i] = *(const float4*)(base + (size_t)c*HW + k4);
    }

    for (int sub = 0; sub < NSUB; sub++) {
        if (sub) __syncthreads();
        #pragma unroll
        for (int i = 0; i < 4; i++) {
            int idx = t + (i << 8);
            int c = idx >> 4, k4 = (idx & 15) << 2;
            s1[i] += v[i].x + v[i].y + v[i].z + v[i].w;
            s2[i] += v[i].x*v[i].x + v[i].y*v[i].y + v[i].z*v[i].z + v[i].w*v[i].w;
            // store tf32-rounded values: one cvt per element, ever
            float4 h = make_float4(f2tff(v[i].x), f2tff(v[i].y),
                                   f2tff(v[i].z), f2tff(v[i].w));
            *(float4*)&As[c*LDA + k4] = h;
        }
        __syncthreads();
        if (sub + 1 < NSUB) {
            #pragma unroll
            for (int i = 0; i < 4; i++) {
                int idx = t + (i << 8);
                int c = idx >> 4, k4 = (idx & 15) << 2;
                v[i] = *(const float4*)(base + (size_t)c*HW + (sub+1)*SUB + k4);
            }
        }

        #pragma unroll
        for (int k0 = 0; k0 < SUB; k0 += 8) {
            int ra = (m0 + gid)*LDA + k0 + tig;
            unsigned ah0 = __float_as_uint(As[ra]);
            unsigned ah1 = __float_as_uint(As[ra + 8*LDA]);
            unsigned ah2 = __float_as_uint(As[ra + 4]);
            unsigned ah3 = __float_as_uint(As[ra + 8*LDA + 4]);
            #pragma unroll
            for (int j = 0; j < 4; j++) {
                int rb = (n0 + 8*j + gid)*LDA + k0 + tig;
                unsigned bh0 = __float_as_uint(As[rb]);
                unsigned bh1 = __float_as_uint(As[rb + 4]);
                mma8(acc[j], ah0, ah1, ah2, ah3, bh0, bh1);
            }
        }
    }

    // per-channel stats: 16 threads share channel c = (t>>4) + 16*i
    #pragma unroll
    for (int i = 0; i < 4; i++) {
        float a = s1[i], b = s2[i];
        #pragma unroll
        for (int off = 8; off >= 1; off >>= 1) {
            a += __shfl_xor_sync(0xffffffffu, a, off, 16);
            b += __shfl_xor_sync(0xffffffffu, b, off, 16);
        }
        if ((t & 15) == 0) {
            int c = (t >> 4) + (i << 4);
            atomicAdd(&g_sum[n*CC + g*DD + c],   a);
            atomicAdd(&g_sumsq[n*CC + g*DD + c], b);
        }
    }
    // Gram accumulation (C frag layout: rows gid/gid+8, cols 2*tig, 2*tig+1)
    float* gg = &g_gram[g*DD*DD];
    #pragma unroll
    for (int j = 0; j < 4; j++) {
        int col = n0 + 8*j + 2*tig;
        atomicAdd(&gg[(m0+gid)*DD   + col],     acc[j][0]);
        atomicAdd(&gg[(m0+gid)*DD   + col + 1], acc[j][1]);
        atomicAdd(&gg[(m0+gid+8)*DD + col],     acc[j][2]);
        atomicAdd(&gg[(m0+gid+8)*DD + col + 1], acc[j][3]);
    }
}

// ---------------------------------------------------------------------------
// Per-n MLP: x_var -> fc1 -> LayerNorm -> relu -> fc2 -> sigmoid = y
__global__ __launch_bounds__(256) void k_reweight(const float* __restrict__ fc1,
                                                  const float* __restrict__ lng,
                                                  const float* __restrict__ lnb,
                                                  const float* __restrict__ fc2) {
    __shared__ float sv[CC];
    __shared__ float sh[DD];
    __shared__ float warpsum[8];
    __shared__ float sred[2];
    int n = blockIdx.x, t = threadIdx.x;

    float s  = g_sum[n*CC + t];
    float ss = g_sumsq[n*CC + t];
    float var = (ss - s*s*(1.0f/HW)) * (1.0f/(HW - 1));   // ddof=1
    sv[t] = var;

    float vs = var;
    #pragma unroll
    for (int o = 16; o; o >>= 1) vs += __shfl_xor_sync(0xffffffffu, vs, o);
    if ((t & 31) == 0) warpsum[t >> 5] = vs;
    __syncthreads();
    if (t == 0) {
        float tot = 0.f;
        #pragma unroll
        for (int i = 0; i < 8; i++) tot += warpsum[i];
        atomicAdd(&g_varsum, tot);
    }

    int w = t >> 5, l = t & 31;
    for (int kk = 0; kk < 8; kk++) {
        int k = w*8 + kk;
        float acc = 0.f;
        for (int c = l; c < CC; c += 32) acc += sv[c] * fc1[k*CC + c];
        #pragma unroll
        for (int o = 16; o; o >>= 1) acc += __shfl_xor_sync(0xffffffffu, acc, o);
        if (l == 0) sh[k] = acc;
    }
    __syncthreads();

    if (w == 0) {
        float h1 = sh[l], h2 = sh[l + 32];
        float su = h1 + h2, q = h1*h1 + h2*h2;
        #pragma unroll
        for (int o = 16; o; o >>= 1) {
            su += __shfl_xor_sync(0xffffffffu, su, o);
            q  += __shfl_xor_sync(0xffffffffu, q,  o);
        }
        float mu = su * (1.0f/DD);
        float vr = q * (1.0f/DD) - mu*mu;
        if (l == 0) { sred[0] = mu; sred[1] = rsqrtf(vr + 1e-5f); }
    }
    __syncthreads();
    float mu = sred[0], rstd = sred[1];
    if (t < DD) {
        float hh = (sh[t] - mu) * rstd * lng[t] + lnb[t];
        sh[t] = fmaxf(hh, 0.f);
    }
    __syncthreads();

    float acc = 0.f;
    #pragma unroll 8
    for (int k = 0; k < DD; k++) acc += sh[k] * fc2[t*DD + k];
    g_y[n*CC + t] = 1.0f / (1.0f + expf(-acc));
}

// ---------------------------------------------------------------------------
// Fused Sigma_N + Newton-Schulz (T=3), tensor-core matmuls with 2-term split
// (accuracy of P multiplies the dominant output branch; keep hi+lo here).
__device__ __forceinline__ void mm_tc(float c[4][4], const float* __restrict__ A,
                                      const float* __restrict__ B,
                                      int m0, int n0, int gid, int tig) {
    #pragma unroll
    for (int j = 0; j < 4; j++)
        #pragma unroll
        for (int q = 0; q < 4; q++) c[j][q] = 0.f;
    #pragma unroll
    for (int k0 = 0; k0 < DD; k0 += 8) {
        float a0r = A[SW(m0+gid,   k0+tig)];
        float a1r = A[SW(m0+gid+8, k0+tig)];
        float a2r = A[SW(m0+gid,   k0+tig+4)];
        float a3r = A[SW(m0+gid+8, k0+tig+4)];
        unsigned ah0 = f2tf(a0r), ah1 = f2tf(a1r), ah2 = f2tf(a2r), ah3 = f2tf(a3r);
        unsigned al0 = __float_as_uint(a0r - __uint_as_float(ah0));
        unsigned al1 = __float_as_uint(a1r - __uint_as_float(ah1));
        unsigned al2 = __float_as_uint(a2r - __uint_as_float(ah2));
        unsigned al3 = __float_as_uint(a3r - __uint_as_float(ah3));
        #pragma unroll
        for (int j = 0; j < 4; j++) {
            unsigned bh0 = f2tf(B[SW(k0+tig,   n0+8*j+gid)]);
            unsigned bh1 = f2tf(B[SW(k0+tig+4, n0+8*j+gid)]);
            mma8(c[j], ah0, ah1, ah2, ah3, bh0, bh1);  // hi*hi
            mma8(c[j], al0, al1, al2, al3, bh0, bh1);  // lo*hi
        }
    }
}

__device__ __forceinline__ void st_tile(float* __restrict__ D, const float c[4][4],
                                        int m0, int n0, int gid, int tig) {
    #pragma unroll
    for (int j = 0; j < 4; j++) {
        int col = n0 + 8*j + 2*tig;
        D[SW(m0+gid,   col)]     = c[j][0];
        D[SW(m0+gid,   col + 1)] = c[j][1];
        D[SW(m0+gid+8, col)]     = c[j][2];
        D[SW(m0+gid+8, col + 1)] = c[j][3];
    }
}

__global__ __launch_bounds__(256) void k_ns(const float* __restrict__ xw) {
    __shared__ float sP[DD*DD];
    __shared__ float sS[DD*DD];
    __shared__ float sT[DD*DD];
    __shared__ float smean[DD];
    __shared__ float strace;
    int g = blockIdx.x, t = threadIdx.x;
    int lane = t & 31, w = t >> 5;
    int gid = lane >> 2, tig = lane & 3;
    int m0 = (w & 3) << 4;
    int n0 = (w >> 2) << 5;

    // ---- build Sigma_N (swizzled) ----
    if (t < DD) {
        float s = 0.f;
        #pragma unroll 8
        for (int n = 0; n < NB; n++) s += g_sum[n*CC + g*DD + t];
        smean[t] = s * (1.0f/(float)MMTOT);
    }
    if (t == 0) strace = 0.f;
    __syncthreads();
    float tr = 0.f;
    #pragma unroll
    for (int i = 0; i < 16; i++) {
        int idx = t + i*256;
        int r = idx >> 6, c = idx & 63;
        float vv = 1e-5f * (g_gram[g*DD*DD + idx] - (float)MMTOT * smean[r] * smean[c]);
        if (r == c) { vv += 1.0f/(float)MMTOT; tr += vv; }
        sS[SW(r,c)] = vv;
        sP[SW(r,c)] = (r == c) ? 1.0f : 0.0f;
    }
    #pragma unroll
    for (int o = 16; o; o >>= 1) tr += __shfl_xor_sync(0xffffffffu, tr, o);
    if ((t & 31) == 0) atomicAdd(&strace, tr);
    __syncthreads();
    float rtr = 1.0f / strace;
    #pragma unroll
    for (int i = 0; i < 16; i++) sS[t + i*256] *= rtr;   // layout-agnostic scale
    __syncthreads();

    // ---- Newton-Schulz, 3 iterations ----
    for (int it = 0; it < 3; it++) {
        float cr[4][4];
        mm_tc(cr, sP, sP, m0, n0, gid, tig);     // T = P@P
        st_tile(sT, cr, m0, n0, gid, tig);
        __syncthreads();                         // bar1: sT writes visible

        mm_tc(cr, sT, sP, m0, n0, gid, tig);     // P3 = T@P (regs)
        float pold[4][4];
        #pragma unroll
        for (int j = 0; j < 4; j++) {
            int col = n0 + 8*j + 2*tig;
            pold[j][0] = sP[SW(m0+gid,   col)];
            pold[j][1] = sP[SW(m0+gid,   col+1)];
            pold[j][2] = sP[SW(m0+gid+8, col)];
            pold[j][3] = sP[SW(m0+gid+8, col+1)];
        }
        __syncthreads();                         // bar2: sT reads done
        st_tile(sT, cr, m0, n0, gid, tig);       // sT <- P3
        __syncthreads();                         // bar3

        mm_tc(cr, sT, sS, m0, n0, gid, tig);     // F = P3@S
        #pragma unroll
        for (int j = 0; j < 4; j++)
            #pragma unroll
            for (int q = 0; q < 4; q++)
                cr[j][q] = -0.5f*pold[j][q] + 1.5f*cr[j][q];
        st_tile(sP, cr, m0, n0, gid, tig);       // P <- update
        __syncthreads();                         // bar4
    }

    float wb = 1.0f / (1.0f + expf(-xw[0]));
    #pragma unroll
    for (int i = 0; i < 16; i++) {
        int idx = t + i*256;
        int r = idx >> 6, c = idx & 63;
        g_pw[g*DD*DD + idx] = wb * sP[SW(r,c)];
    }
}

// ---------------------------------------------------------------------------
// Pass 2: out = wP@X + coef.*X. P hi-fragments preloaded in registers; smem
// tile holds tf32-PRE-ROUNDED X, so inner loop is pure LDS+mma. The residual
// branch uses the tf32-rounded X (error ~2^-13, diluted by the blend).
// Grid: (CHUNKS, GG, NB), 256 threads.
__global__ __launch_bounds__(256, 3) void k_apply(const float* __restrict__ X,
                                                  const float* __restrict__ xw,
                                                  float* __restrict__ out) {
    __shared__ float Xs[DD*LDB];
    int n = blockIdx.z, g = blockIdx.y, chn = blockIdx.x;
    const float* base = X   + ((size_t)(n*CC + g*DD))*HW + (size_t)chn*TK;
    float*      obase = out + ((size_t)(n*CC + g*DD))*HW + (size_t)chn*TK;
    int t = threadIdx.x, lane = t & 31, w = t >> 5;
    int gid = lane >> 2, tig = lane & 3;
    int m0 = (w & 3) << 4;
    int nw0 = (w >> 2) << 5;

    // preload wP hi fragments into registers (rows m0+gid/+8, k-tiles 0..7)
    unsigned pah[8][4];
    const float* P = &g_pw[g*DD*DD];
    #pragma unroll
    for (int kt = 0; kt < 8; kt++) {
        int k0 = kt*8;
        pah[kt][0] = f2tf(P[(m0+gid)*DD   + k0 + tig]);
        pah[kt][1] = f2tf(P[(m0+gid+8)*DD + k0 + tig]);
        pah[kt][2] = f2tf(P[(m0+gid)*DD   + k0 + tig + 4]);
        pah[kt][3] = f2tf(P[(m0+gid+8)*DD + k0 + tig + 4]);
    }
    float wblend = 1.0f / (1.0f + expf(-xw[0]));
    float rscale = rsqrtf(g_varsum * (1.0f/(float)(NB*CC)));
    float coef0 = (1.0f - wblend) * g_y[n*CC + g*DD + m0 + gid]     * rscale;
    float coef1 = (1.0f - wblend) * g_y[n*CC + g*DD + m0 + gid + 8] * rscale;

    // prefetch subtile 0
    float4 v[4];
    #pragma unroll
    for (int i = 0; i < 4; i++) {
        int idx = t + (i << 8);
        int c = idx >> 4, k4 = (idx & 15) << 2;
        v[i] = *(const float4*)(base + (size_t)c*HW + k4);
    }

    for (int sub = 0; sub < NSUB; sub++) {
        if (sub) __syncthreads();
        #pragma unroll
        for (int i = 0; i < 4; i++) {
            int idx = t + (i << 8);
            int c = idx >> 4, k4 = (idx & 15) << 2;
            float4 h = make_float4(f2tff(v[i].x), f2tff(v[i].y),
                                   f2tff(v[i].z), f2tff(v[i].w));
            *(float4*)&Xs[c*LDB + k4] = h;
        }
        __syncthreads();
        if (sub + 1 < NSUB) {
            #pragma unroll
            for (int i = 0; i < 4; i++) {
                int idx = t + (i << 8);
                int c = idx >> 4, k4 = (idx & 15) << 2;
                v[i] = *(const float4*)(base + (size_t)c*HW + (sub+1)*SUB + k4);
            }
        }

        float acc[4][4];
        #pragma unroll
        for (int j = 0; j < 4; j++)
            #pragma unroll
            for (int q = 0; q < 4; q++) acc[j][q] = 0.f;

        #pragma unroll
        for (int kt = 0; kt < 8; kt++) {
            int k0 = kt*8;
            #pragma unroll
            for (int j = 0; j < 4; j++) {
                int rb = (k0 + tig)*LDB + nw0 + 8*j + gid;
                unsigned bh0 = __float_as_uint(Xs[rb]);
                unsigned bh1 = __float_as_uint(Xs[rb + 4*LDB]);
                mma8(acc[j], pah[kt][0], pah[kt][1], pah[kt][2], pah[kt][3], bh0, bh1);
            }
        }

        // epilogue: residual uses tf32-rounded X from smem
        #pragma unroll
        for (int j = 0; j < 4; j++) {
            int col = nw0 + 8*j + 2*tig;
            int r1 = m0 + gid, r2 = r1 + 8;
            float x10 = Xs[r1*LDB + col],     x11 = Xs[r1*LDB + col + 1];
            float x20 = Xs[r2*LDB + col],     x21 = Xs[r2*LDB + col + 1];
            float2 o1 = make_float2(acc[j][0] + coef0*x10, acc[j][1] + coef0*x11);
            float2 o2 = make_float2(acc[j][2] + coef1*x20, acc[j][3] + coef1*x21);
            *(float2*)(obase + (size_t)r1*HW + sub*SUB + col) = o1;
            *(float2*)(obase + (size_t)r2*HW + sub*SUB + col) = o2;
        }
    }
}

// ---------------------------------------------------------------------------
extern "C" void kernel_launch(void* const* d_in, const int* in_sizes, int n_in,
                              void* d_out, int out_size) {
    const float* X   = (const float*)d_in[0];
    const float* fc1 = (const float*)d_in[1];
    const float* lng = (const float*)d_in[2];
    const float* lnb = (const float*)d_in[3];
    const float* fc2 = (const float*)d_in[4];
    const float* xw  = (const float*)d_in[5];
    float* out = (float*)d_out;

    k_zero<<<64, 256>>>();
    dim3 grid(CHUNKS, GG, NB);
    k_statsgram<<<grid, 256>>>(X);
    k_reweight<<<NB, 256>>>(fc1, lng, lnb, fc2);
    k_ns<<<GG, 256>>>(xw);
    k_apply<<<grid, 256>>>(X, xw, out);
}